// round 4
// baseline (speedup 1.0000x reference)
#include <cuda_runtime.h>
#include <math.h>
#include <stdint.h>

#define PIX 4096
#define NV 9

// ---------------- scratch (device globals; no allocations allowed) ----------
__device__ float g_x  [32ull*64*PIX];   // encoder output x (fp32 addend)
__device__ float g_e1 [32ull*32*PIX];   // encoder stage 1 (tf32-rounded)
__device__ float g_e2 [32ull*64*PIX];   // encoder stage 2 (tf32-rounded)
__device__ float g_h0 [2ull*36*64*PIX]; // ping-pong h0 (tf32-rounded)
__device__ float g_h1 [2ull*36*64*PIX]; // ping-pong h1
__device__ float g_up [36ull*64*PIX];   // layer-1 conv_u output (fp32 addend)
// permuted tf32 weights: [tap][k][nperm], nperm=(n%8)*8+n/8
__device__ float g_wp2 [9*32*64];
__device__ float g_wp3 [9*64*64];
__device__ float g_wpul[9*64*64];
__device__ float g_wph0[9*64*64];
__device__ float g_wph1[9*64*64];

__global__ void zero_init_k() {
    size_t i = (size_t)blockIdx.x * 256 + threadIdx.x;   // 9216*256 threads
    float4 z = make_float4(0.f, 0.f, 0.f, 0.f);
    reinterpret_cast<float4*>(g_h0)[i] = z;
    reinterpret_cast<float4*>(g_h1)[i] = z;
}

// ---------------- helpers ----------------------------------------------------
__device__ __forceinline__ float rna(float x) {
    unsigned r;
    asm("cvt.rna.tf32.f32 %0, %1;" : "=r"(r) : "f"(x));
    return __uint_as_float(r);
}
__device__ __forceinline__ void cp16(uint32_t s, const float* g, int srcsz) {
    asm volatile("cp.async.ca.shared.global [%0], [%1], 16, %2;"
                 :: "r"(s), "l"(g), "r"(srcsz));
}
__device__ __forceinline__ void cp8(uint32_t s, const float* g, int srcsz) {
    asm volatile("cp.async.ca.shared.global [%0], [%1], 8, %2;"
                 :: "r"(s), "l"(g), "r"(srcsz));
}
__device__ __forceinline__ void cp_commit() { asm volatile("cp.async.commit_group;"); }
__device__ __forceinline__ void cp_wait()   { asm volatile("cp.async.wait_all;" ::: "memory"); }

__device__ __forceinline__ void mma8(float* d, unsigned a0, unsigned a1,
                                     unsigned a2, unsigned a3,
                                     unsigned b0, unsigned b1) {
    asm("mma.sync.aligned.m16n8k8.row.col.f32.tf32.tf32.f32 "
        "{%0,%1,%2,%3},{%4,%5,%6,%7},{%8,%9},{%0,%1,%2,%3};"
        : "+f"(d[0]), "+f"(d[1]), "+f"(d[2]), "+f"(d[3])
        : "r"(a0), "r"(a1), "r"(a2), "r"(a3), "r"(b0), "r"(b1));
}

// ---------------- weight permute+round prep ----------------------------------
__global__ void prep_w_k(const float* __restrict__ w2, const float* __restrict__ w3,
                         const float* __restrict__ wul, const float* __restrict__ wh0,
                         const float* __restrict__ wh1) {
    int idx = blockIdx.x * 256 + threadIdx.x;
    int conv = blockIdx.y;
    const float* src; float* dst; int CIN;
    if      (conv == 0) { src = w2;  dst = g_wp2;  CIN = 32; }
    else if (conv == 1) { src = w3;  dst = g_wp3;  CIN = 64; }
    else if (conv == 2) { src = wul; dst = g_wpul; CIN = 64; }
    else if (conv == 3) { src = wh0; dst = g_wph0; CIN = 64; }
    else                { src = wh1; dst = g_wph1; CIN = 64; }
    int total = 9 * CIN * 64;
    if (idx >= total) return;
    int tap = idx / (CIN * 64), rem = idx - tap * (CIN * 64);
    int k = rem / 64, np = rem & 63;
    int n = ((np & 7) << 3) + (np >> 3);
    dst[idx] = rna(src[((size_t)n * CIN + k) * 9 + tap]);
}

// ---------------- encoder conv1: 3->32, 5x5, zero pad 2, BN+ReLU -------------
__global__ void __launch_bounds__(256, 2)
conv1_k(const float* __restrict__ u, const float* __restrict__ wt,
        const float* __restrict__ gm, const float* __restrict__ bt,
        float* __restrict__ out) {
    __shared__ float sIn[400];       // 20x20 tile (halo 2)
    __shared__ float sW[25 * 32];    // [tap][cout]
    int tile = blockIdx.x, e = blockIdx.y;      // e = t*4 + b
    int tstep = e >> 2, bb = e & 3;
    int ty0 = (tile >> 2) << 4, tx0 = (tile & 3) << 4;
    int tid = threadIdx.x, lx = tid & 15, ly = tid >> 4;
    const float* inImg = u + (size_t)(bb * 8 + tstep) * 3 * PIX;  // u[b][t][c]
    float acc[32];
#pragma unroll
    for (int c = 0; c < 32; c++) acc[c] = 0.f;

    for (int k = 0; k < 3; k++) {
        const float* inC = inImg + (size_t)k * PIX;
        for (int i = tid; i < 400; i += 256) {
            int ry = i / 20, rx = i - ry * 20;
            int gy = ty0 + ry - 2, gx = tx0 + rx - 2;
            sIn[i] = (gy >= 0 && gy < 64 && gx >= 0 && gx < 64) ? inC[gy * 64 + gx] : 0.f;
        }
        for (int i = tid; i < 800; i += 256) {
            int c = i / 25, t5 = i - c * 25;
            sW[t5 * 32 + c] = wt[(c * 3 + k) * 25 + t5];
        }
        __syncthreads();
        float n[25];
#pragma unroll
        for (int dy = 0; dy < 5; dy++)
#pragma unroll
            for (int dx = 0; dx < 5; dx++)
                n[dy * 5 + dx] = sIn[(ly + dy) * 20 + lx + dx];
#pragma unroll
        for (int t5 = 0; t5 < 25; t5++) {
            const float4* w4 = (const float4*)(sW + t5 * 32);
            float nb = n[t5];
#pragma unroll
            for (int cc = 0; cc < 8; cc++) {
                float4 w = w4[cc];
                acc[cc * 4 + 0] += nb * w.x;
                acc[cc * 4 + 1] += nb * w.y;
                acc[cc * 4 + 2] += nb * w.z;
                acc[cc * 4 + 3] += nb * w.w;
            }
        }
        __syncthreads();
    }
    int pix = (ty0 + ly) * 64 + tx0 + lx;
    const float BNS = 0.9999950000374996f;   // 1/sqrt(1+1e-5)
    float* o = out + (size_t)e * 32 * PIX + pix;
#pragma unroll
    for (int c = 0; c < 32; c++) {
        float r = acc[c] * (gm[c] * BNS) + bt[c];
        o[(size_t)c * PIX] = rna(fmaxf(r, 0.f));   // feeds mma -> tf32 round
    }
}

// ---------------- tensor-core 3x3 conv, CIN->64, K-split --------------------
// Block: 512 thr = 16 warps; 4 output rows (256 px), all 64 couts.
// Warp w: slot = w>>1 -> (row = slot>>2? no: slot>>1 = row, slot&1 = xhalf);
//         kpar = w&1 splits the cin reduction (even/odd groups of 8).
// After mainloop, warp pairs exchange partial accs via smem (stride-33,
// conflict-free) reusing the A region; each warp finishes epilogue for mt=kpar.
// EPI 0: BN+ReLU (RNA opt)   EPI 1: tanh(acc+x), rna   EPI 2: tanh(acc+up) + d_out
template <int CIN, bool CIRC, int EPI, bool RNA>
__global__ void __launch_bounds__(512, 1)
convmma_k(const float* __restrict__ in, const float* __restrict__ wp,
          const float* __restrict__ gm, const float* __restrict__ bt,
          const float* __restrict__ add, float* __restrict__ out,
          float* __restrict__ out2, int tstep) {
    constexpr int TAPCH = (CIN == 64) ? 3 : 9;   // taps per W chunk
    constexpr int NCH = 9 / TAPCH;
    constexpr int AROW = 584;                    // k-stride (words)
    extern __shared__ float sm[];
    float* As = sm;                      // [CIN][AROW]
    float* Ws = sm + CIN * AROW;         // [TAPCH][CIN][64]

    int img = blockIdx.y, ry0 = blockIdx.x * 4;
    int tid = threadIdx.x;
    int w = tid >> 5, lane = tid & 31, qp = (tid >> 2) & 7, qt = tid & 3;
    int slot = w >> 1, kpar = w & 1;
    int row = slot >> 1, xhalf = slot & 1;
    int vy = 0, vx = 0;
    if (CIRC) { int v = img % NV; vy = v / 3 - 1; vx = v % 3 - 1; }
    const float* inI = in + (size_t)img * CIN * PIX;
    uint32_t smA = (uint32_t)__cvta_generic_to_shared(As);
    uint32_t smW = (uint32_t)__cvta_generic_to_shared(Ws);

    // ---- stage A: rows ry0-2..ry0+3, cols -2..65 (wrap or zero) ----
    for (int i = tid; i < CIN * 144; i += 512) {     // CIN*8*18 slots
        int k = i / 144, rem = i - k * 144, r = rem / 18, s = rem - r * 18;
        int gy = ry0 + r - 2;
        bool rowok = true;
        if (CIRC) gy &= 63; else rowok = (gy >= 0 && gy < 64);
        const float* srow = inI + (size_t)k * PIX + gy * 64;
        uint32_t dst = smA + (uint32_t)(k * AROW + r * 72) * 4u;
        if (s < 16)      cp16(dst + (4 + s * 4) * 4, srow + s * 4, rowok ? 16 : 0);
        else if (s == 16) cp8(dst + 2 * 4, srow + 62, CIRC ? 8 : 0);   // gx -2,-1
        else              cp8(dst + 68 * 4, srow,     CIRC ? 8 : 0);   // gx 64,65
    }
    // ---- stage W chunk 0 ----
    {
        const float4* src = (const float4*)wp;
        for (int i = tid; i < TAPCH * CIN * 16; i += 512)
            cp16(smW + i * 16, (const float*)(src + i), 16);
    }
    cp_commit(); cp_wait(); __syncthreads();

    float acc[2][8][4];
#pragma unroll
    for (int mt = 0; mt < 2; mt++)
#pragma unroll
        for (int g = 0; g < 8; g++)
#pragma unroll
            for (int j = 0; j < 4; j++) acc[mt][g][j] = 0.f;

    int mbase = (2 + row) * 72 + 4 + 32 * xhalf + qp;
    const unsigned* Au = (const unsigned*)As;

    for (int ch = 0; ch < NCH; ch++) {
        if (ch) {
            __syncthreads();
            const float4* src = (const float4*)(wp + (size_t)ch * TAPCH * CIN * 64);
            for (int i = tid; i < TAPCH * CIN * 16; i += 512)
                cp16(smW + i * 16, (const float*)(src + i), 16);
            cp_commit(); cp_wait(); __syncthreads();
        }
#pragma unroll
        for (int tapc = 0; tapc < TAPCH; tapc++) {
            int tap = ch * TAPCH + tapc;
            int dy = tap / 3, dx = tap - dy * 3;
            int apos = mbase + (dy - 1 + vy) * 72 + (dx - 1 + vx);
#pragma unroll
            for (int ks2 = 0; ks2 < CIN / 16; ks2++) {
                int ks = ks2 * 2 + kpar;             // K-split: even/odd groups
                int kr0 = ks * 8 + qt, kr1 = kr0 + 4;
                const uint4* B0 = (const uint4*)(Ws + (tapc * CIN + kr0) * 64 + qp * 8);
                const uint4* B1 = (const uint4*)(Ws + (tapc * CIN + kr1) * 64 + qp * 8);
                uint4 l0 = B0[0], l1 = B0[1], h0 = B1[0], h1 = B1[1];
                unsigned blo[8] = {l0.x, l0.y, l0.z, l0.w, l1.x, l1.y, l1.z, l1.w};
                unsigned bhi[8] = {h0.x, h0.y, h0.z, h0.w, h1.x, h1.y, h1.z, h1.w};
                unsigned a[2][4];
#pragma unroll
                for (int mt = 0; mt < 2; mt++) {
                    int base = apos + mt * 16;
                    a[mt][0] = Au[kr0 * AROW + base];
                    a[mt][1] = Au[kr0 * AROW + base + 8];
                    a[mt][2] = Au[kr1 * AROW + base];
                    a[mt][3] = Au[kr1 * AROW + base + 8];
                }
#pragma unroll
                for (int g = 0; g < 8; g++)
#pragma unroll
                    for (int mt = 0; mt < 2; mt++)
                        mma8(acc[mt][g], a[mt][0], a[mt][1], a[mt][2], a[mt][3],
                             blo[g], bhi[g]);
            }
        }
    }

    // ---- K-split reduction: exchange the partner's mt via smem (reuse As) ----
    __syncthreads();                       // everyone done reading As/Ws
    {
        float* Rs = sm;
        int rbase = (w * 32 + lane) * 33;
        int po = 1 - 2 * kpar;             // partner warp offset (+1 / -1)
        int prbase = ((w + po) * 32 + lane) * 33;
#pragma unroll
        for (int g = 0; g < 8; g++)
#pragma unroll
            for (int j = 0; j < 4; j++)
                Rs[rbase + g * 4 + j] = acc[1 - kpar][g][j];
        __syncthreads();
#pragma unroll
        for (int g = 0; g < 8; g++)
#pragma unroll
            for (int j = 0; j < 4; j++)
                acc[kpar][g][j] += Rs[prbase + g * 4 + j];
    }

    // ---- epilogue: warp handles mt = kpar ----
    int mt = kpar;
    int y = ry0 + row;
    int x0 = 32 * xhalf + qp + mt * 16;
    int pixA = y * 64 + x0, pixB = pixA + 8;
    const float BNS = 0.9999950000374996f;
#pragma unroll
    for (int g = 0; g < 8; g++) {
        int c = g * 8 + qt * 2;
        float v0 = acc[mt][g][0], v1 = acc[mt][g][1];
        float v2 = acc[mt][g][2], v3 = acc[mt][g][3];
        if (EPI == 0) {
            float s0 = gm[c] * BNS, s1 = gm[c + 1] * BNS;
            float o0 = bt[c], o1 = bt[c + 1];
            float r0 = fmaxf(v0 * s0 + o0, 0.f), r1 = fmaxf(v1 * s1 + o1, 0.f);
            float r2 = fmaxf(v2 * s0 + o0, 0.f), r3 = fmaxf(v3 * s1 + o1, 0.f);
            float* p0 = out + ((size_t)img * 64 + c) * PIX;
            float* p1 = p0 + PIX;
            if (RNA) { r0 = rna(r0); r1 = rna(r1); r2 = rna(r2); r3 = rna(r3); }
            p0[pixA] = r0; p0[pixB] = r2; p1[pixA] = r1; p1[pixB] = r3;
        } else if (EPI == 1) {
            const float* a0 = add + ((size_t)(tstep * 4 + img / NV) * 64 + c) * PIX;
            const float* a1 = a0 + PIX;
            float t0 = tanhf(v0 + a0[pixA]), t1 = tanhf(v1 + a1[pixA]);
            float t2 = tanhf(v2 + a0[pixB]), t3 = tanhf(v3 + a1[pixB]);
            float* p0 = out + ((size_t)img * 64 + c) * PIX;
            float* p1 = p0 + PIX;
            p0[pixA] = rna(t0); p0[pixB] = rna(t2);
            p1[pixA] = rna(t1); p1[pixB] = rna(t3);
        } else {
            const float* a0 = add + ((size_t)img * 64 + c) * PIX;
            const float* a1 = a0 + PIX;
            float t0 = tanhf(v0 + a0[pixA]), t1 = tanhf(v1 + a1[pixA]);
            float t2 = tanhf(v2 + a0[pixB]), t3 = tanhf(v3 + a1[pixB]);
            float* p0 = out + ((size_t)img * 64 + c) * PIX;
            float* p1 = p0 + PIX;
            p0[pixA] = rna(t0); p0[pixB] = rna(t2);
            p1[pixA] = rna(t1); p1[pixB] = rna(t3);
            int v9 = img % NV, bb = img / NV;
            float* q0 = out2 + (((size_t)(v9 * 4 + bb) * 64 + c) * 8 + tstep) * PIX;
            float* q1 = q0 + 8 * PIX;
            q0[pixA] = t0; q0[pixB] = t2; q1[pixA] = t1; q1[pixB] = t3;
        }
    }
}

// ---------------- host driver -------------------------------------------------
extern "C" void kernel_launch(void* const* d_in, const int* in_sizes, int n_in,
                              void* d_out, int out_size) {
    (void)in_sizes; (void)n_in; (void)out_size;
    const float* u   = (const float*)d_in[0];
    const float* w1  = (const float*)d_in[1];
    const float* g1  = (const float*)d_in[2];
    const float* b1  = (const float*)d_in[3];
    const float* w2  = (const float*)d_in[4];
    const float* g2  = (const float*)d_in[5];
    const float* b2  = (const float*)d_in[6];
    const float* w3  = (const float*)d_in[7];
    const float* g3  = (const float*)d_in[8];
    const float* b3  = (const float*)d_in[9];
    const float* wul = (const float*)d_in[10];
    const float* gul = (const float*)d_in[11];
    const float* bul = (const float*)d_in[12];
    const float* wh0 = (const float*)d_in[13];
    const float* wh1 = (const float*)d_in[14];
    float* out = (float*)d_out;

    const int SM32B = (32 * 584 + 9 * 32 * 64) * 4;   // 148480
    const int SM64B = (64 * 584 + 3 * 64 * 64) * 4;   // 198656

    static float *px = nullptr, *pe1 = nullptr, *pe2 = nullptr,
                 *ph0 = nullptr, *ph1 = nullptr, *pup = nullptr,
                 *pw2 = nullptr, *pw3 = nullptr, *pwul = nullptr,
                 *pwh0 = nullptr, *pwh1 = nullptr;
    if (!px) {   // pointer caching + attribute setup; runs on the pre-capture call
        cudaGetSymbolAddress((void**)&px,   g_x);
        cudaGetSymbolAddress((void**)&pe1,  g_e1);
        cudaGetSymbolAddress((void**)&pe2,  g_e2);
        cudaGetSymbolAddress((void**)&ph0,  g_h0);
        cudaGetSymbolAddress((void**)&ph1,  g_h1);
        cudaGetSymbolAddress((void**)&pup,  g_up);
        cudaGetSymbolAddress((void**)&pw2,  g_wp2);
        cudaGetSymbolAddress((void**)&pw3,  g_wp3);
        cudaGetSymbolAddress((void**)&pwul, g_wpul);
        cudaGetSymbolAddress((void**)&pwh0, g_wph0);
        cudaGetSymbolAddress((void**)&pwh1, g_wph1);
        cudaFuncSetAttribute(convmma_k<32, false, 0, true>,
                             cudaFuncAttributeMaxDynamicSharedMemorySize, SM32B);
        cudaFuncSetAttribute(convmma_k<64, false, 0, false>,
                             cudaFuncAttributeMaxDynamicSharedMemorySize, SM64B);
        cudaFuncSetAttribute(convmma_k<64, true, 1, false>,
                             cudaFuncAttributeMaxDynamicSharedMemorySize, SM64B);
        cudaFuncSetAttribute(convmma_k<64, true, 2, false>,
                             cudaFuncAttributeMaxDynamicSharedMemorySize, SM64B);
    }
    const size_t HSZ = 36ull * 64 * PIX;

    zero_init_k<<<9216, 256>>>();
    prep_w_k<<<dim3(144, 5), 256>>>(w2, w3, wul, wh0, wh1);

    // encoder for all (t,b) up front
    conv1_k<<<dim3(16, 32), 256>>>(u, w1, g1, b1, pe1);
    convmma_k<32, false, 0, true ><<<dim3(16, 32), 512, SM32B>>>(
        pe1, pw2, g2, b2, nullptr, pe2, nullptr, 0);
    convmma_k<64, false, 0, false><<<dim3(16, 32), 512, SM64B>>>(
        pe2, pw3, g3, b3, nullptr, px, nullptr, 0);

    // recurrent steps
    for (int t = 0; t < 8; t++) {
        int rp = t & 1, wp = 1 - rp;
        // h0 = tanh(x_t + circ-shift conv(h0_old, w_h0))
        convmma_k<64, true, 1, false><<<dim3(16, 36), 512, SM64B>>>(
            ph0 + rp * HSZ, pwh0, nullptr, nullptr, px, ph0 + wp * HSZ, nullptr, t);
        // up = relu(bn(conv(h0_new, w_ul)))  (zero pad, fp32 addend out)
        convmma_k<64, false, 0, false><<<dim3(16, 36), 512, SM64B>>>(
            ph0 + wp * HSZ, pwul, gul, bul, nullptr, pup, nullptr, 0);
        // h1 = tanh(up + circ-shift conv(h1_old, w_h1)); fused d_out store
        convmma_k<64, true, 2, false><<<dim3(16, 36), 512, SM64B>>>(
            ph1 + rp * HSZ, pwh1, nullptr, nullptr, pup, ph1 + wp * HSZ, out, t);
    }
}

// round 5
// speedup vs baseline: 1.0011x; 1.0011x over previous
#include <cuda_runtime.h>
#include <math.h>
#include <stdint.h>

#define PIX 4096
#define NV 9

// ---------------- scratch (device globals; no allocations allowed) ----------
__device__ float g_x  [32ull*64*PIX];   // encoder output x (fp32 addend)
__device__ float g_e1 [32ull*32*PIX];   // encoder stage 1 (tf32-rounded)
__device__ float g_e2 [32ull*64*PIX];   // encoder stage 2 (tf32-rounded)
__device__ float g_h0 [2ull*36*64*PIX]; // ping-pong h0 (tf32-rounded)
__device__ float g_h1 [2ull*36*64*PIX]; // ping-pong h1
__device__ float g_up [36ull*64*PIX];   // layer-1 conv_u output (fp32 addend)
// permuted tf32 weights: [tap][k][nperm], nperm=(n%8)*8+n/8
__device__ float g_wp2 [9*32*64];
__device__ float g_wp3 [9*64*64];
__device__ float g_wpul[9*64*64];
__device__ float g_wph0[9*64*64];
__device__ float g_wph1[9*64*64];

__global__ void zero_init_k() {
    size_t i = (size_t)blockIdx.x * 256 + threadIdx.x;   // 9216*256 threads
    float4 z = make_float4(0.f, 0.f, 0.f, 0.f);
    reinterpret_cast<float4*>(g_h0)[i] = z;
    reinterpret_cast<float4*>(g_h1)[i] = z;
}

// ---------------- helpers ----------------------------------------------------
__device__ __forceinline__ float rna(float x) {
    unsigned r;
    asm("cvt.rna.tf32.f32 %0, %1;" : "=r"(r) : "f"(x));
    return __uint_as_float(r);
}
__device__ __forceinline__ void cp16(uint32_t s, const float* g, int srcsz) {
    asm volatile("cp.async.ca.shared.global [%0], [%1], 16, %2;"
                 :: "r"(s), "l"(g), "r"(srcsz));
}
__device__ __forceinline__ void cp8(uint32_t s, const float* g, int srcsz) {
    asm volatile("cp.async.ca.shared.global [%0], [%1], 8, %2;"
                 :: "r"(s), "l"(g), "r"(srcsz));
}
__device__ __forceinline__ void cp_commit() { asm volatile("cp.async.commit_group;"); }
__device__ __forceinline__ void cp_wait()   { asm volatile("cp.async.wait_all;" ::: "memory"); }

__device__ __forceinline__ void mma8(float* d, unsigned a0, unsigned a1,
                                     unsigned a2, unsigned a3,
                                     unsigned b0, unsigned b1) {
    asm("mma.sync.aligned.m16n8k8.row.col.f32.tf32.tf32.f32 "
        "{%0,%1,%2,%3},{%4,%5,%6,%7},{%8,%9},{%0,%1,%2,%3};"
        : "+f"(d[0]), "+f"(d[1]), "+f"(d[2]), "+f"(d[3])
        : "r"(a0), "r"(a1), "r"(a2), "r"(a3), "r"(b0), "r"(b1));
}

// ---------------- weight permute+round prep ----------------------------------
__global__ void prep_w_k(const float* __restrict__ w2, const float* __restrict__ w3,
                         const float* __restrict__ wul, const float* __restrict__ wh0,
                         const float* __restrict__ wh1) {
    int idx = blockIdx.x * 256 + threadIdx.x;
    int conv = blockIdx.y;
    const float* src; float* dst; int CIN;
    if      (conv == 0) { src = w2;  dst = g_wp2;  CIN = 32; }
    else if (conv == 1) { src = w3;  dst = g_wp3;  CIN = 64; }
    else if (conv == 2) { src = wul; dst = g_wpul; CIN = 64; }
    else if (conv == 3) { src = wh0; dst = g_wph0; CIN = 64; }
    else                { src = wh1; dst = g_wph1; CIN = 64; }
    int total = 9 * CIN * 64;
    if (idx >= total) return;
    int tap = idx / (CIN * 64), rem = idx - tap * (CIN * 64);
    int k = rem / 64, np = rem & 63;
    int n = ((np & 7) << 3) + (np >> 3);
    dst[idx] = rna(src[((size_t)n * CIN + k) * 9 + tap]);
}

// ---------------- encoder conv1: 3->32, 5x5, zero pad 2, BN+ReLU -------------
__global__ void __launch_bounds__(256, 2)
conv1_k(const float* __restrict__ u, const float* __restrict__ wt,
        const float* __restrict__ gm, const float* __restrict__ bt,
        float* __restrict__ out) {
    __shared__ float sIn[400];       // 20x20 tile (halo 2)
    __shared__ float sW[25 * 32];    // [tap][cout]
    int tile = blockIdx.x, e = blockIdx.y;      // e = t*4 + b
    int tstep = e >> 2, bb = e & 3;
    int ty0 = (tile >> 2) << 4, tx0 = (tile & 3) << 4;
    int tid = threadIdx.x, lx = tid & 15, ly = tid >> 4;
    const float* inImg = u + (size_t)(bb * 8 + tstep) * 3 * PIX;  // u[b][t][c]
    float acc[32];
#pragma unroll
    for (int c = 0; c < 32; c++) acc[c] = 0.f;

    for (int k = 0; k < 3; k++) {
        const float* inC = inImg + (size_t)k * PIX;
        for (int i = tid; i < 400; i += 256) {
            int ry = i / 20, rx = i - ry * 20;
            int gy = ty0 + ry - 2, gx = tx0 + rx - 2;
            sIn[i] = (gy >= 0 && gy < 64 && gx >= 0 && gx < 64) ? inC[gy * 64 + gx] : 0.f;
        }
        for (int i = tid; i < 800; i += 256) {
            int c = i / 25, t5 = i - c * 25;
            sW[t5 * 32 + c] = wt[(c * 3 + k) * 25 + t5];
        }
        __syncthreads();
        float n[25];
#pragma unroll
        for (int dy = 0; dy < 5; dy++)
#pragma unroll
            for (int dx = 0; dx < 5; dx++)
                n[dy * 5 + dx] = sIn[(ly + dy) * 20 + lx + dx];
#pragma unroll
        for (int t5 = 0; t5 < 25; t5++) {
            const float4* w4 = (const float4*)(sW + t5 * 32);
            float nb = n[t5];
#pragma unroll
            for (int cc = 0; cc < 8; cc++) {
                float4 w = w4[cc];
                acc[cc * 4 + 0] += nb * w.x;
                acc[cc * 4 + 1] += nb * w.y;
                acc[cc * 4 + 2] += nb * w.z;
                acc[cc * 4 + 3] += nb * w.w;
            }
        }
        __syncthreads();
    }
    int pix = (ty0 + ly) * 64 + tx0 + lx;
    const float BNS = 0.9999950000374996f;   // 1/sqrt(1+1e-5)
    float* o = out + (size_t)e * 32 * PIX + pix;
#pragma unroll
    for (int c = 0; c < 32; c++) {
        float r = acc[c] * (gm[c] * BNS) + bt[c];
        o[(size_t)c * PIX] = rna(fmaxf(r, 0.f));   // feeds mma -> tf32 round
    }
}

// ---------------- tensor-core 3x3 conv, CIN->64, K-split --------------------
// Block: 512 thr = 16 warps; 4 output rows (256 px), all 64 couts.
// Warp w: slot = w>>1 -> (row = slot>>2? no: slot>>1 = row, slot&1 = xhalf);
//         kpar = w&1 splits the cin reduction (even/odd groups of 8).
// After mainloop, warp pairs exchange partial accs via smem (stride-33,
// conflict-free) reusing the A region; each warp finishes epilogue for mt=kpar.
// EPI 0: BN+ReLU (RNA opt)   EPI 1: tanh(acc+x), rna   EPI 2: tanh(acc+up) + d_out
template <int CIN, bool CIRC, int EPI, bool RNA>
__global__ void __launch_bounds__(512, 1)
convmma_k(const float* __restrict__ in, const float* __restrict__ wp,
          const float* __restrict__ gm, const float* __restrict__ bt,
          const float* __restrict__ add, float* __restrict__ out,
          float* __restrict__ out2, int tstep) {
    constexpr int TAPCH = (CIN == 64) ? 3 : 9;   // taps per W chunk
    constexpr int NCH = 9 / TAPCH;
    constexpr int AROW = 584;                    // k-stride (words)
    extern __shared__ float sm[];
    float* As = sm;                      // [CIN][AROW]
    float* Ws = sm + CIN * AROW;         // [TAPCH][CIN][64]

    int img = blockIdx.y, ry0 = blockIdx.x * 4;
    int tid = threadIdx.x;
    int w = tid >> 5, lane = tid & 31, qp = (tid >> 2) & 7, qt = tid & 3;
    int slot = w >> 1, kpar = w & 1;
    int row = slot >> 1, xhalf = slot & 1;
    int vy = 0, vx = 0;
    if (CIRC) { int v = img % NV; vy = v / 3 - 1; vx = v % 3 - 1; }
    const float* inI = in + (size_t)img * CIN * PIX;
    uint32_t smA = (uint32_t)__cvta_generic_to_shared(As);
    uint32_t smW = (uint32_t)__cvta_generic_to_shared(Ws);

    // ---- stage A: rows ry0-2..ry0+3, cols -2..65 (wrap or zero) ----
    for (int i = tid; i < CIN * 144; i += 512) {     // CIN*8*18 slots
        int k = i / 144, rem = i - k * 144, r = rem / 18, s = rem - r * 18;
        int gy = ry0 + r - 2;
        bool rowok = true;
        if (CIRC) gy &= 63; else rowok = (gy >= 0 && gy < 64);
        const float* srow = inI + (size_t)k * PIX + gy * 64;
        uint32_t dst = smA + (uint32_t)(k * AROW + r * 72) * 4u;
        if (s < 16)      cp16(dst + (4 + s * 4) * 4, srow + s * 4, rowok ? 16 : 0);
        else if (s == 16) cp8(dst + 2 * 4, srow + 62, CIRC ? 8 : 0);   // gx -2,-1
        else              cp8(dst + 68 * 4, srow,     CIRC ? 8 : 0);   // gx 64,65
    }
    // ---- stage W chunk 0 ----
    {
        const float4* src = (const float4*)wp;
        for (int i = tid; i < TAPCH * CIN * 16; i += 512)
            cp16(smW + i * 16, (const float*)(src + i), 16);
    }
    cp_commit(); cp_wait(); __syncthreads();

    float acc[2][8][4];
#pragma unroll
    for (int mt = 0; mt < 2; mt++)
#pragma unroll
        for (int g = 0; g < 8; g++)
#pragma unroll
            for (int j = 0; j < 4; j++) acc[mt][g][j] = 0.f;

    int mbase = (2 + row) * 72 + 4 + 32 * xhalf + qp;
    const unsigned* Au = (const unsigned*)As;

    for (int ch = 0; ch < NCH; ch++) {
        if (ch) {
            __syncthreads();
            const float4* src = (const float4*)(wp + (size_t)ch * TAPCH * CIN * 64);
            for (int i = tid; i < TAPCH * CIN * 16; i += 512)
                cp16(smW + i * 16, (const float*)(src + i), 16);
            cp_commit(); cp_wait(); __syncthreads();
        }
#pragma unroll
        for (int tapc = 0; tapc < TAPCH; tapc++) {
            int tap = ch * TAPCH + tapc;
            int dy = tap / 3, dx = tap - dy * 3;
            int apos = mbase + (dy - 1 + vy) * 72 + (dx - 1 + vx);
#pragma unroll
            for (int ks2 = 0; ks2 < CIN / 16; ks2++) {
                int ks = ks2 * 2 + kpar;             // K-split: even/odd groups
                int kr0 = ks * 8 + qt, kr1 = kr0 + 4;
                const uint4* B0 = (const uint4*)(Ws + (tapc * CIN + kr0) * 64 + qp * 8);
                const uint4* B1 = (const uint4*)(Ws + (tapc * CIN + kr1) * 64 + qp * 8);
                uint4 l0 = B0[0], l1 = B0[1], h0 = B1[0], h1 = B1[1];
                unsigned blo[8] = {l0.x, l0.y, l0.z, l0.w, l1.x, l1.y, l1.z, l1.w};
                unsigned bhi[8] = {h0.x, h0.y, h0.z, h0.w, h1.x, h1.y, h1.z, h1.w};
                unsigned a[2][4];
#pragma unroll
                for (int mt = 0; mt < 2; mt++) {
                    int base = apos + mt * 16;
                    a[mt][0] = Au[kr0 * AROW + base];
                    a[mt][1] = Au[kr0 * AROW + base + 8];
                    a[mt][2] = Au[kr1 * AROW + base];
                    a[mt][3] = Au[kr1 * AROW + base + 8];
                }
#pragma unroll
                for (int g = 0; g < 8; g++)
#pragma unroll
                    for (int mt = 0; mt < 2; mt++)
                        mma8(acc[mt][g], a[mt][0], a[mt][1], a[mt][2], a[mt][3],
                             blo[g], bhi[g]);
            }
        }
    }

    // ---- K-split reduction: exchange the partner's mt via smem (reuse As) ----
    __syncthreads();                       // everyone done reading As/Ws
    {
        float* Rs = sm;
        int rbase = (w * 32 + lane) * 33;
        int po = 1 - 2 * kpar;             // partner warp offset (+1 / -1)
        int prbase = ((w + po) * 32 + lane) * 33;
#pragma unroll
        for (int g = 0; g < 8; g++)
#pragma unroll
            for (int j = 0; j < 4; j++)
                Rs[rbase + g * 4 + j] = acc[1 - kpar][g][j];
        __syncthreads();
#pragma unroll
        for (int g = 0; g < 8; g++)
#pragma unroll
            for (int j = 0; j < 4; j++)
                acc[kpar][g][j] += Rs[prbase + g * 4 + j];
    }

    // ---- epilogue: warp handles mt = kpar ----
    int mt = kpar;
    int y = ry0 + row;
    int x0 = 32 * xhalf + qp + mt * 16;
    int pixA = y * 64 + x0, pixB = pixA + 8;
    const float BNS = 0.9999950000374996f;
#pragma unroll
    for (int g = 0; g < 8; g++) {
        int c = g * 8 + qt * 2;
        float v0 = acc[mt][g][0], v1 = acc[mt][g][1];
        float v2 = acc[mt][g][2], v3 = acc[mt][g][3];
        if (EPI == 0) {
            float s0 = gm[c] * BNS, s1 = gm[c + 1] * BNS;
            float o0 = bt[c], o1 = bt[c + 1];
            float r0 = fmaxf(v0 * s0 + o0, 0.f), r1 = fmaxf(v1 * s1 + o1, 0.f);
            float r2 = fmaxf(v2 * s0 + o0, 0.f), r3 = fmaxf(v3 * s1 + o1, 0.f);
            float* p0 = out + ((size_t)img * 64 + c) * PIX;
            float* p1 = p0 + PIX;
            if (RNA) { r0 = rna(r0); r1 = rna(r1); r2 = rna(r2); r3 = rna(r3); }
            p0[pixA] = r0; p0[pixB] = r2; p1[pixA] = r1; p1[pixB] = r3;
        } else if (EPI == 1) {
            const float* a0 = add + ((size_t)(tstep * 4 + img / NV) * 64 + c) * PIX;
            const float* a1 = a0 + PIX;
            float t0 = tanhf(v0 + a0[pixA]), t1 = tanhf(v1 + a1[pixA]);
            float t2 = tanhf(v2 + a0[pixB]), t3 = tanhf(v3 + a1[pixB]);
            float* p0 = out + ((size_t)img * 64 + c) * PIX;
            float* p1 = p0 + PIX;
            p0[pixA] = rna(t0); p0[pixB] = rna(t2);
            p1[pixA] = rna(t1); p1[pixB] = rna(t3);
        } else {
            const float* a0 = add + ((size_t)img * 64 + c) * PIX;
            const float* a1 = a0 + PIX;
            float t0 = tanhf(v0 + a0[pixA]), t1 = tanhf(v1 + a1[pixA]);
            float t2 = tanhf(v2 + a0[pixB]), t3 = tanhf(v3 + a1[pixB]);
            float* p0 = out + ((size_t)img * 64 + c) * PIX;
            float* p1 = p0 + PIX;
            p0[pixA] = rna(t0); p0[pixB] = rna(t2);
            p1[pixA] = rna(t1); p1[pixB] = rna(t3);
            int v9 = img % NV, bb = img / NV;
            float* q0 = out2 + (((size_t)(v9 * 4 + bb) * 64 + c) * 8 + tstep) * PIX;
            float* q1 = q0 + 8 * PIX;
            q0[pixA] = t0; q0[pixB] = t2; q1[pixA] = t1; q1[pixB] = t3;
        }
    }
}

// ---------------- host driver -------------------------------------------------
extern "C" void kernel_launch(void* const* d_in, const int* in_sizes, int n_in,
                              void* d_out, int out_size) {
    (void)in_sizes; (void)n_in; (void)out_size;
    const float* u   = (const float*)d_in[0];
    const float* w1  = (const float*)d_in[1];
    const float* g1  = (const float*)d_in[2];
    const float* b1  = (const float*)d_in[3];
    const float* w2  = (const float*)d_in[4];
    const float* g2  = (const float*)d_in[5];
    const float* b2  = (const float*)d_in[6];
    const float* w3  = (const float*)d_in[7];
    const float* g3  = (const float*)d_in[8];
    const float* b3  = (const float*)d_in[9];
    const float* wul = (const float*)d_in[10];
    const float* gul = (const float*)d_in[11];
    const float* bul = (const float*)d_in[12];
    const float* wh0 = (const float*)d_in[13];
    const float* wh1 = (const float*)d_in[14];
    float* out = (float*)d_out;

    const int SM32B = (32 * 584 + 9 * 32 * 64) * 4;   // 148480
    const int SM64B = (64 * 584 + 3 * 64 * 64) * 4;   // 198656

    static float *px = nullptr, *pe1 = nullptr, *pe2 = nullptr,
                 *ph0 = nullptr, *ph1 = nullptr, *pup = nullptr,
                 *pw2 = nullptr, *pw3 = nullptr, *pwul = nullptr,
                 *pwh0 = nullptr, *pwh1 = nullptr;
    if (!px) {   // pointer caching + attribute setup; runs on the pre-capture call
        cudaGetSymbolAddress((void**)&px,   g_x);
        cudaGetSymbolAddress((void**)&pe1,  g_e1);
        cudaGetSymbolAddress((void**)&pe2,  g_e2);
        cudaGetSymbolAddress((void**)&ph0,  g_h0);
        cudaGetSymbolAddress((void**)&ph1,  g_h1);
        cudaGetSymbolAddress((void**)&pup,  g_up);
        cudaGetSymbolAddress((void**)&pw2,  g_wp2);
        cudaGetSymbolAddress((void**)&pw3,  g_wp3);
        cudaGetSymbolAddress((void**)&pwul, g_wpul);
        cudaGetSymbolAddress((void**)&pwh0, g_wph0);
        cudaGetSymbolAddress((void**)&pwh1, g_wph1);
        cudaFuncSetAttribute(convmma_k<32, false, 0, true>,
                             cudaFuncAttributeMaxDynamicSharedMemorySize, SM32B);
        cudaFuncSetAttribute(convmma_k<64, false, 0, false>,
                             cudaFuncAttributeMaxDynamicSharedMemorySize, SM64B);
        cudaFuncSetAttribute(convmma_k<64, true, 1, false>,
                             cudaFuncAttributeMaxDynamicSharedMemorySize, SM64B);
        cudaFuncSetAttribute(convmma_k<64, true, 2, false>,
                             cudaFuncAttributeMaxDynamicSharedMemorySize, SM64B);
    }
    const size_t HSZ = 36ull * 64 * PIX;

    zero_init_k<<<9216, 256>>>();
    prep_w_k<<<dim3(144, 5), 256>>>(w2, w3, wul, wh0, wh1);

    // encoder for all (t,b) up front
    conv1_k<<<dim3(16, 32), 256>>>(u, w1, g1, b1, pe1);
    convmma_k<32, false, 0, true ><<<dim3(16, 32), 512, SM32B>>>(
        pe1, pw2, g2, b2, nullptr, pe2, nullptr, 0);
    convmma_k<64, false, 0, false><<<dim3(16, 32), 512, SM64B>>>(
        pe2, pw3, g3, b3, nullptr, px, nullptr, 0);

    // recurrent steps
    for (int t = 0; t < 8; t++) {
        int rp = t & 1, wp = 1 - rp;
        // h0 = tanh(x_t + circ-shift conv(h0_old, w_h0))
        convmma_k<64, true, 1, false><<<dim3(16, 36), 512, SM64B>>>(
            ph0 + rp * HSZ, pwh0, nullptr, nullptr, px, ph0 + wp * HSZ, nullptr, t);
        // up = relu(bn(conv(h0_new, w_ul)))  (zero pad, fp32 addend out)
        convmma_k<64, false, 0, false><<<dim3(16, 36), 512, SM64B>>>(
            ph0 + wp * HSZ, pwul, gul, bul, nullptr, pup, nullptr, 0);
        // h1 = tanh(up + circ-shift conv(h1_old, w_h1)); fused d_out store
        convmma_k<64, true, 2, false><<<dim3(16, 36), 512, SM64B>>>(
            ph1 + rp * HSZ, pwh1, nullptr, nullptr, pup, ph1 + wp * HSZ, out, t);
    }
}

// round 7
// speedup vs baseline: 2.9837x; 2.9806x over previous
#include <cuda_runtime.h>
#include <cuda_fp16.h>
#include <math.h>
#include <stdint.h>

#define PIX 4096
#define NV 9

// ---------------- scratch (device globals; half2 feature buffers) ------------
__device__ unsigned g_e1[32ull*16*PIX];     // encoder stage1, 32ch = 16 kpairs
__device__ unsigned g_e2[32ull*32*PIX];     // encoder stage2, 64ch = 32 kpairs
__device__ unsigned g_h0[2ull*36*32*PIX];   // ping-pong h0 (half2)
__device__ unsigned g_h1[2ull*36*32*PIX];   // ping-pong h1 (half2)
__device__ float    g_x [32ull*32*PIX*2];   // fp32 addend x, float2-interleaved
__device__ float    g_up[36ull*32*PIX*2];   // fp32 addend up
// pre-permuted half2 weights, conflict-free smem image (row stride 104 u32)
__device__ unsigned g_wp2 [144*104];
__device__ unsigned g_wp3 [288*104];
__device__ unsigned g_wpul[288*104];
__device__ unsigned g_wph0[288*104];
__device__ unsigned g_wph1[288*104];

// ---------------- helpers -----------------------------------------------------
__device__ __forceinline__ void cp16(uint32_t s, const void* g, int srcsz) {
    asm volatile("cp.async.ca.shared.global [%0], [%1], 16, %2;"
                 :: "r"(s), "l"(g), "r"(srcsz));
}
__device__ __forceinline__ void cp8(uint32_t s, const void* g, int srcsz) {
    asm volatile("cp.async.ca.shared.global [%0], [%1], 8, %2;"
                 :: "r"(s), "l"(g), "r"(srcsz));
}
#define CP_COMMIT() asm volatile("cp.async.commit_group;")
#define CP_WAIT0()  asm volatile("cp.async.wait_group 0;" ::: "memory")

__device__ __forceinline__ void mma16(float* d, unsigned a0, unsigned a1,
                                      unsigned a2, unsigned a3,
                                      unsigned b0, unsigned b1) {
    asm("mma.sync.aligned.m16n8k16.row.col.f32.f16.f16.f32 "
        "{%0,%1,%2,%3},{%4,%5,%6,%7},{%8,%9},{%0,%1,%2,%3};"
        : "+f"(d[0]), "+f"(d[1]), "+f"(d[2]), "+f"(d[3])
        : "r"(a0), "r"(a1), "r"(a2), "r"(a3), "r"(b0), "r"(b1));
}
__device__ __forceinline__ unsigned packh(float a, float b) {
    __half2 h = __halves2half2(__float2half_rn(a), __float2half_rn(b));
    return *(unsigned*)&h;
}
__constant__ float BNS_C = 0.9999950000374996f;   // 1/sqrt(1+1e-5)

__global__ void zero4_k(float4* p, long n) {
    long i = (long)blockIdx.x * 256 + threadIdx.x, s = (long)gridDim.x * 256;
    float4 z = make_float4(0.f, 0.f, 0.f, 0.f);
    for (; i < n; i += s) p[i] = z;
}

// weights -> half2, permuted: row = (tap*KT+kt)*8+kp8 (stride 104), col gid*12+g
__global__ void prep_w_k(const float* __restrict__ w2, const float* __restrict__ w3,
                         const float* __restrict__ wul, const float* __restrict__ wh0,
                         const float* __restrict__ wh1) {
    int idx = blockIdx.x * 256 + threadIdx.x, conv = blockIdx.y;
    const float* src; unsigned* dst; int CIN;
    if      (conv == 0) { src = w2;  dst = g_wp2;  CIN = 32; }
    else if (conv == 1) { src = w3;  dst = g_wp3;  CIN = 64; }
    else if (conv == 2) { src = wul; dst = g_wpul; CIN = 64; }
    else if (conv == 3) { src = wh0; dst = g_wph0; CIN = 64; }
    else                { src = wh1; dst = g_wph1; CIN = 64; }
    int KP = CIN >> 1, KT = CIN >> 4;
    if (idx >= 9 * KP * 64) return;
    int tap = idx / (KP * 64), rem = idx - tap * (KP * 64);
    int kp = rem >> 6, n = rem & 63;
    int kt = kp >> 3, kp8 = kp & 7, gid = n & 7, g = n >> 3;
    float lo = src[((size_t)n * CIN + 2 * kp) * 9 + tap];
    float hi = src[((size_t)n * CIN + 2 * kp + 1) * 9 + tap];
    dst[((tap * KT + kt) * 8 + kp8) * 104 + gid * 12 + g] = packh(lo, hi);
}

// ---------------- encoder conv1: 3->32, 5x5, zero pad 2, BN+ReLU -------------
__global__ void __launch_bounds__(256, 2)
conv1_k(const float* __restrict__ u, const float* __restrict__ wt,
        const float* __restrict__ gm, const float* __restrict__ bt,
        unsigned* __restrict__ out) {
    __shared__ float sIn[400];
    __shared__ float sW[25 * 32];
    int tile = blockIdx.x, e = blockIdx.y;      // e = t*4+b
    int tstep = e >> 2, bb = e & 3;
    int ty0 = (tile >> 2) << 4, tx0 = (tile & 3) << 4;
    int tid = threadIdx.x, lx = tid & 15, ly = tid >> 4;
    const float* inImg = u + (size_t)(bb * 8 + tstep) * 3 * PIX;
    float acc[32];
#pragma unroll
    for (int c = 0; c < 32; c++) acc[c] = 0.f;
    for (int k = 0; k < 3; k++) {
        const float* inC = inImg + (size_t)k * PIX;
        for (int i = tid; i < 400; i += 256) {
            int ry = i / 20, rx = i - ry * 20;
            int gy = ty0 + ry - 2, gx = tx0 + rx - 2;
            sIn[i] = (gy >= 0 && gy < 64 && gx >= 0 && gx < 64) ? inC[gy * 64 + gx] : 0.f;
        }
        for (int i = tid; i < 800; i += 256) {
            int c = i / 25, t5 = i - c * 25;
            sW[t5 * 32 + c] = wt[(c * 3 + k) * 25 + t5];
        }
        __syncthreads();
        float n[25];
#pragma unroll
        for (int dy = 0; dy < 5; dy++)
#pragma unroll
            for (int dx = 0; dx < 5; dx++)
                n[dy * 5 + dx] = sIn[(ly + dy) * 20 + lx + dx];
#pragma unroll
        for (int t5 = 0; t5 < 25; t5++) {
            const float4* w4 = (const float4*)(sW + t5 * 32);
            float nb = n[t5];
#pragma unroll
            for (int cc = 0; cc < 8; cc++) {
                float4 w = w4[cc];
                acc[cc*4+0] += nb*w.x; acc[cc*4+1] += nb*w.y;
                acc[cc*4+2] += nb*w.z; acc[cc*4+3] += nb*w.w;
            }
        }
        __syncthreads();
    }
    int pix = (ty0 + ly) * 64 + tx0 + lx;
    unsigned* o = out + (size_t)e * 16 * PIX + pix;
#pragma unroll
    for (int p = 0; p < 16; p++) {
        float r0 = fmaxf(acc[2*p]   * (gm[2*p]   * BNS_C) + bt[2*p],   0.f);
        float r1 = fmaxf(acc[2*p+1] * (gm[2*p+1] * BNS_C) + bt[2*p+1], 0.f);
        o[(size_t)p * PIX] = packh(r0, r1);
    }
}

// ---------------- fp16 tensor-core 3x3 conv, CIN->64 -------------------------
// Block 256 thr = 8 warps; 4 output rows x 64 px, all 64 couts per warp-slot.
// A smem: [KP kpairs][584] (8 rows x 72 px, halo 2; wrap/zero + velocity at
// staging). W smem: all 9 taps, conflict-free layout. Zero mainloop barriers.
// EPI 0: BN+ReLU -> half2    EPI 1: BN+ReLU -> float2 addend
// EPI 2: tanh(acc + x) -> half2    EPI 3: tanh(acc + up) -> half2 + d_out fp32
template <int CIN, bool CIRC, int EPI>
__global__ void __launch_bounds__(256, 1)
convh_k(const unsigned* __restrict__ in, const unsigned* __restrict__ wp,
        const float* __restrict__ gm, const float* __restrict__ bt,
        const float* __restrict__ add, unsigned* __restrict__ outH,
        float* __restrict__ outF, float* __restrict__ out2, int tstep) {
    constexpr int KP = CIN / 2, KT = CIN / 16;
    extern __shared__ unsigned smu[];
    unsigned* As = smu;                  // [KP][584]
    unsigned* Ws = smu + KP * 584;       // [KT*9*8 rows][104]

    int img = blockIdx.y, ry0 = blockIdx.x * 4;
    int tid = threadIdx.x;
    int w = tid >> 5, qp = (tid >> 2) & 7, qt = tid & 3;
    int row = w >> 1, xhalf = w & 1;
    int vy = 0, vx = 0;
    if (CIRC) { int v = img % NV; vy = v / 3 - 1; vx = v % 3 - 1; }
    const unsigned* inI = in + (size_t)img * KP * PIX;
    uint32_t smA = (uint32_t)__cvta_generic_to_shared(As);
    uint32_t smW = (uint32_t)__cvta_generic_to_shared(Ws);

    // ---- stage A: rows ry0-2..ry0+5, cols -2..65 (wrap or zero) ----
    for (int i = tid; i < KP * 144; i += 256) {
        int k = i / 144, rem = i - k * 144, r = rem / 18, s = rem - r * 18;
        int gy = ry0 + r - 2;
        bool rowok = true;
        if (CIRC) gy &= 63; else rowok = (gy >= 0 && gy < 64);
        const unsigned* srow = inI + (size_t)k * PIX + gy * 64;
        uint32_t dst = smA + (uint32_t)(k * 584 + r * 72) * 4u;
        if (s < 16)       cp16(dst + (4 + s * 4) * 4, srow + s * 4, rowok ? 16 : 0);
        else if (s == 16) cp8(dst + 2 * 4, srow + 62, CIRC ? 8 : 0);
        else              cp8(dst + 68 * 4, srow,     CIRC ? 8 : 0);
    }
    // ---- stage all 9 tap weight images (linear copy incl. padding) ----
    for (int i = tid; i < KT * 9 * 8 * 26; i += 256)
        cp16(smW + i * 16, wp + i * 4, 16);
    CP_COMMIT(); CP_WAIT0(); __syncthreads();

    float acc[2][8][4];
#pragma unroll
    for (int mt = 0; mt < 2; mt++)
#pragma unroll
        for (int g = 0; g < 8; g++)
#pragma unroll
            for (int j = 0; j < 4; j++) acc[mt][g][j] = 0.f;

    int mbase = (2 + row) * 72 + 4 + 32 * xhalf + qp;

#pragma unroll
    for (int tap = 0; tap < 9; tap++) {
        int dy = tap / 3, dx = tap - dy * 3;
        int apos = mbase + (dy - 1 + vy) * 72 + (dx - 1 + vx);
#pragma unroll
        for (int kt = 0; kt < KT; kt++) {
            int wr = ((tap * KT + kt) * 8 + qt) * 104 + qp * 12;
            uint4 L0 = *(const uint4*)(Ws + wr);
            uint4 L1 = *(const uint4*)(Ws + wr + 4);
            uint4 L2 = *(const uint4*)(Ws + wr + 4 * 104);
            uint4 L3 = *(const uint4*)(Ws + wr + 4 * 104 + 4);
            unsigned b0[8] = {L0.x, L0.y, L0.z, L0.w, L1.x, L1.y, L1.z, L1.w};
            unsigned b1[8] = {L2.x, L2.y, L2.z, L2.w, L3.x, L3.y, L3.z, L3.w};
            int ar0 = (kt * 8 + qt) * 584, ar2 = ar0 + 4 * 584;
#pragma unroll
            for (int mt = 0; mt < 2; mt++) {
                int base = apos + mt * 16;
                unsigned a0 = As[ar0 + base], a1 = As[ar0 + base + 8];
                unsigned a2 = As[ar2 + base], a3 = As[ar2 + base + 8];
#pragma unroll
                for (int g = 0; g < 8; g++)
                    mma16(acc[mt][g], a0, a1, a2, a3, b0[g], b1[g]);
            }
        }
    }

    // ---- epilogue ----
    int y = ry0 + row;
#pragma unroll
    for (int mt = 0; mt < 2; mt++) {
        int x0 = 32 * xhalf + qp + mt * 16;
        int pixA = y * 64 + x0, pixB = pixA + 8;
#pragma unroll
        for (int g = 0; g < 8; g++) {
            int kp = g * 4 + qt, c = kp * 2;
            float v0 = acc[mt][g][0], v1 = acc[mt][g][1];
            float v2 = acc[mt][g][2], v3 = acc[mt][g][3];
            if (EPI == 0 || EPI == 1) {
                float s0 = gm[c] * BNS_C, s1 = gm[c+1] * BNS_C;
                float o0 = bt[c], o1 = bt[c+1];
                v0 = fmaxf(v0 * s0 + o0, 0.f); v1 = fmaxf(v1 * s1 + o1, 0.f);
                v2 = fmaxf(v2 * s0 + o0, 0.f); v3 = fmaxf(v3 * s1 + o1, 0.f);
                if (EPI == 0) {
                    unsigned* o = outH + ((size_t)img * 32 + kp) * PIX;
                    o[pixA] = packh(v0, v1); o[pixB] = packh(v2, v3);
                } else {
                    float2* o = (float2*)outF + ((size_t)img * 32 + kp) * PIX;
                    o[pixA] = make_float2(v0, v1); o[pixB] = make_float2(v2, v3);
                }
            } else {
                const float2* a = (const float2*)add +
                    ((EPI == 2) ? ((size_t)(tstep * 4 + img / NV) * 32 + kp) * PIX
                                : ((size_t)img * 32 + kp) * PIX);
                float2 xa = a[pixA], xb = a[pixB];
                float t0 = tanhf(v0 + xa.x), t1 = tanhf(v1 + xa.y);
                float t2 = tanhf(v2 + xb.x), t3 = tanhf(v3 + xb.y);
                unsigned* o = outH + ((size_t)img * 32 + kp) * PIX;
                o[pixA] = packh(t0, t1); o[pixB] = packh(t2, t3);
                if (EPI == 3) {
                    int v9 = img % NV, bb = img / NV;
                    float* q = out2 + (((size_t)(v9 * 4 + bb) * 64 + c) * 8 + tstep) * PIX;
                    q[pixA] = t0; q[pixB] = t2;
                    q += 8 * PIX;
                    q[pixA] = t1; q[pixB] = t3;
                }
            }
        }
    }
}

// ---------------- host driver -------------------------------------------------
extern "C" void kernel_launch(void* const* d_in, const int* in_sizes, int n_in,
                              void* d_out, int out_size) {
    (void)in_sizes; (void)n_in; (void)out_size;
    const float* u   = (const float*)d_in[0];
    const float* w1  = (const float*)d_in[1];
    const float* g1  = (const float*)d_in[2];
    const float* b1  = (const float*)d_in[3];
    const float* w2  = (const float*)d_in[4];
    const float* g2  = (const float*)d_in[5];
    const float* b2  = (const float*)d_in[6];
    const float* w3  = (const float*)d_in[7];
    const float* g3  = (const float*)d_in[8];
    const float* b3  = (const float*)d_in[9];
    const float* wul = (const float*)d_in[10];
    const float* gul = (const float*)d_in[11];
    const float* bul = (const float*)d_in[12];
    const float* wh0 = (const float*)d_in[13];
    const float* wh1 = (const float*)d_in[14];
    float* out = (float*)d_out;

    const int SM64B = (32 * 584 + 288 * 104) * 4;   // 194560
    const int SM32B = (16 * 584 + 144 * 104) * 4;   // 97280

    static unsigned *pe1 = nullptr, *pe2, *ph0, *ph1,
                    *pw2, *pw3, *pwul, *pwh0, *pwh1;
    static float *px, *pup;
    if (!pe1) {   // pointer caching + attrs; runs on the pre-capture call
        cudaGetSymbolAddress((void**)&pe1,  g_e1);
        cudaGetSymbolAddress((void**)&pe2,  g_e2);
        cudaGetSymbolAddress((void**)&ph0,  g_h0);
        cudaGetSymbolAddress((void**)&ph1,  g_h1);
        cudaGetSymbolAddress((void**)&px,   g_x);
        cudaGetSymbolAddress((void**)&pup,  g_up);
        cudaGetSymbolAddress((void**)&pw2,  g_wp2);
        cudaGetSymbolAddress((void**)&pw3,  g_wp3);
        cudaGetSymbolAddress((void**)&pwul, g_wpul);
        cudaGetSymbolAddress((void**)&pwh0, g_wph0);
        cudaGetSymbolAddress((void**)&pwh1, g_wph1);
        cudaFuncSetAttribute(convh_k<32, false, 0>,
                             cudaFuncAttributeMaxDynamicSharedMemorySize, SM32B);
        cudaFuncSetAttribute(convh_k<64, false, 1>,
                             cudaFuncAttributeMaxDynamicSharedMemorySize, SM64B);
        cudaFuncSetAttribute(convh_k<64, true, 2>,
                             cudaFuncAttributeMaxDynamicSharedMemorySize, SM64B);
        cudaFuncSetAttribute(convh_k<64, true, 3>,
                             cudaFuncAttributeMaxDynamicSharedMemorySize, SM64B);
    }
    const size_t HSZ = 36ull * 32 * PIX;   // h buffer parity size (u32 units)

    // zero parity-0 h states (half2 zeros == bit-zero)
    zero4_k<<<1536, 256>>>((float4*)ph0, (long)HSZ / 4);
    zero4_k<<<1536, 256>>>((float4*)ph1, (long)HSZ / 4);
    prep_w_k<<<dim3(72, 5), 256>>>(w2, w3, wul, wh0, wh1);

    // encoder
    conv1_k<<<dim3(16, 32), 256>>>(u, w1, g1, b1, pe1);
    convh_k<32, false, 0><<<dim3(16, 32), 256, SM32B>>>(
        pe1, pw2, g2, b2, nullptr, pe2, nullptr, nullptr, 0);
    convh_k<64, false, 1><<<dim3(16, 32), 256, SM64B>>>(
        pe2, pw3, g3, b3, nullptr, nullptr, px, nullptr, 0);

    // recurrent steps
    for (int t = 0; t < 8; t++) {
        int rp = t & 1, wpp = 1 - rp;
        // h0 = tanh(x_t + circ-shift conv(h0_old, w_h0))
        convh_k<64, true, 2><<<dim3(16, 36), 256, SM64B>>>(
            ph0 + rp * HSZ, pwh0, nullptr, nullptr, px,
            ph0 + wpp * HSZ, nullptr, nullptr, t);
        // up = relu(bn(conv(h0_new, w_ul)))  (zero pad, float2 addend out)
        convh_k<64, false, 1><<<dim3(16, 36), 256, SM64B>>>(
            ph0 + wpp * HSZ, pwul, gul, bul, nullptr, nullptr, pup, nullptr, 0);
        // h1 = tanh(up + circ-shift conv(h1_old, w_h1)); fused d_out store
        convh_k<64, true, 3><<<dim3(16, 36), 256, SM64B>>>(
            ph1 + rp * HSZ, pwh1, nullptr, nullptr, pup,
            ph1 + wpp * HSZ, nullptr, out, t);
    }
}

// round 8
// speedup vs baseline: 3.4833x; 1.1674x over previous
#include <cuda_runtime.h>
#include <cuda_fp16.h>
#include <math.h>
#include <stdint.h>

#define PIX 4096
#define NV 9

// ---------------- scratch (device globals; half2 feature buffers) ------------
__device__ unsigned g_e1[32ull*16*PIX];     // encoder stage1, 32ch = 16 kpairs
__device__ unsigned g_e2[32ull*32*PIX];     // encoder stage2, 64ch = 32 kpairs
__device__ unsigned g_h0[2ull*36*32*PIX];   // ping-pong h0 (half2)
__device__ unsigned g_h1[2ull*36*32*PIX];   // ping-pong h1 (half2)
__device__ float    g_x [32ull*32*PIX*2];   // fp32 addend x, float2-interleaved
__device__ float    g_up[36ull*32*PIX*2];   // fp32 addend up
// pre-permuted half2 weights, conflict-free smem image (row stride 100 u32)
__device__ unsigned g_wp2 [144*100];
__device__ unsigned g_wp3 [288*100];
__device__ unsigned g_wpul[288*100];
__device__ unsigned g_wph0[288*100];
__device__ unsigned g_wph1[288*100];

// ---------------- helpers -----------------------------------------------------
__device__ __forceinline__ void cp16(uint32_t s, const void* g, int srcsz) {
    asm volatile("cp.async.ca.shared.global [%0], [%1], 16, %2;"
                 :: "r"(s), "l"(g), "r"(srcsz));
}
__device__ __forceinline__ void cp8(uint32_t s, const void* g, int srcsz) {
    asm volatile("cp.async.ca.shared.global [%0], [%1], 8, %2;"
                 :: "r"(s), "l"(g), "r"(srcsz));
}
#define CP_COMMIT() asm volatile("cp.async.commit_group;")
#define CP_WAIT0()  asm volatile("cp.async.wait_group 0;" ::: "memory")

__device__ __forceinline__ void mma16(float* d, unsigned a0, unsigned a1,
                                      unsigned a2, unsigned a3,
                                      unsigned b0, unsigned b1) {
    asm("mma.sync.aligned.m16n8k16.row.col.f32.f16.f16.f32 "
        "{%0,%1,%2,%3},{%4,%5,%6,%7},{%8,%9},{%0,%1,%2,%3};"
        : "+f"(d[0]), "+f"(d[1]), "+f"(d[2]), "+f"(d[3])
        : "r"(a0), "r"(a1), "r"(a2), "r"(a3), "r"(b0), "r"(b1));
}
__device__ __forceinline__ unsigned packh(float a, float b) {
    __half2 h = __halves2half2(__float2half_rn(a), __float2half_rn(b));
    return *(unsigned*)&h;
}
__constant__ float BNS_C = 0.9999950000374996f;   // 1/sqrt(1+1e-5)

__global__ void zero4_k(float4* p, long n) {
    long i = (long)blockIdx.x * 256 + threadIdx.x, s = (long)gridDim.x * 256;
    float4 z = make_float4(0.f, 0.f, 0.f, 0.f);
    for (; i < n; i += s) p[i] = z;
}

// weights -> half2, permuted: row = (tap*KT+kt)*8+kp8 (stride 100), col gid*12+g
__global__ void prep_w_k(const float* __restrict__ w2, const float* __restrict__ w3,
                         const float* __restrict__ wul, const float* __restrict__ wh0,
                         const float* __restrict__ wh1) {
    int idx = blockIdx.x * 256 + threadIdx.x, conv = blockIdx.y;
    const float* src; unsigned* dst; int CIN;
    if      (conv == 0) { src = w2;  dst = g_wp2;  CIN = 32; }
    else if (conv == 1) { src = w3;  dst = g_wp3;  CIN = 64; }
    else if (conv == 2) { src = wul; dst = g_wpul; CIN = 64; }
    else if (conv == 3) { src = wh0; dst = g_wph0; CIN = 64; }
    else                { src = wh1; dst = g_wph1; CIN = 64; }
    int KP = CIN >> 1, KT = CIN >> 4;
    if (idx >= 9 * KP * 64) return;
    int tap = idx / (KP * 64), rem = idx - tap * (KP * 64);
    int kp = rem >> 6, n = rem & 63;
    int kt = kp >> 3, kp8 = kp & 7, gid = n & 7, g = n >> 3;
    float lo = src[((size_t)n * CIN + 2 * kp) * 9 + tap];
    float hi = src[((size_t)n * CIN + 2 * kp + 1) * 9 + tap];
    dst[((tap * KT + kt) * 8 + kp8) * 100 + gid * 12 + g] = packh(lo, hi);
}

// ---------------- encoder conv1: 3->32, 5x5, zero pad 2, BN+ReLU -------------
__global__ void __launch_bounds__(256, 2)
conv1_k(const float* __restrict__ u, const float* __restrict__ wt,
        const float* __restrict__ gm, const float* __restrict__ bt,
        unsigned* __restrict__ out) {
    __shared__ float sIn[400];
    __shared__ float sW[25 * 32];
    int tile = blockIdx.x, e = blockIdx.y;      // e = t*4+b
    int tstep = e >> 2, bb = e & 3;
    int ty0 = (tile >> 2) << 4, tx0 = (tile & 3) << 4;
    int tid = threadIdx.x, lx = tid & 15, ly = tid >> 4;
    const float* inImg = u + (size_t)(bb * 8 + tstep) * 3 * PIX;
    float acc[32];
#pragma unroll
    for (int c = 0; c < 32; c++) acc[c] = 0.f;
    for (int k = 0; k < 3; k++) {
        const float* inC = inImg + (size_t)k * PIX;
        for (int i = tid; i < 400; i += 256) {
            int ry = i / 20, rx = i - ry * 20;
            int gy = ty0 + ry - 2, gx = tx0 + rx - 2;
            sIn[i] = (gy >= 0 && gy < 64 && gx >= 0 && gx < 64) ? inC[gy * 64 + gx] : 0.f;
        }
        for (int i = tid; i < 800; i += 256) {
            int c = i / 25, t5 = i - c * 25;
            sW[t5 * 32 + c] = wt[(c * 3 + k) * 25 + t5];
        }
        __syncthreads();
        float n[25];
#pragma unroll
        for (int dy = 0; dy < 5; dy++)
#pragma unroll
            for (int dx = 0; dx < 5; dx++)
                n[dy * 5 + dx] = sIn[(ly + dy) * 20 + lx + dx];
#pragma unroll
        for (int t5 = 0; t5 < 25; t5++) {
            const float4* w4 = (const float4*)(sW + t5 * 32);
            float nb = n[t5];
#pragma unroll
            for (int cc = 0; cc < 8; cc++) {
                float4 w = w4[cc];
                acc[cc*4+0] += nb*w.x; acc[cc*4+1] += nb*w.y;
                acc[cc*4+2] += nb*w.z; acc[cc*4+3] += nb*w.w;
            }
        }
        __syncthreads();
    }
    int pix = (ty0 + ly) * 64 + tx0 + lx;
    unsigned* o = out + (size_t)e * 16 * PIX + pix;
#pragma unroll
    for (int p = 0; p < 16; p++) {
        float r0 = fmaxf(acc[2*p]   * (gm[2*p]   * BNS_C) + bt[2*p],   0.f);
        float r1 = fmaxf(acc[2*p+1] * (gm[2*p+1] * BNS_C) + bt[2*p+1], 0.f);
        o[(size_t)p * PIX] = packh(r0, r1);
    }
}

// ---------------- fp16 tensor-core 3x3 conv, CIN->64 -------------------------
// Block 512 thr = 16 warps; 8 output rows x 64 px; warp = (row 0..7, xhalf).
// A smem: [KP kpairs][872] (12 rows x 72 px, halo 2; wrap/zero + velocity at
// staging). W smem: all 9 taps, stride-100 conflict-free. No mainloop barriers.
// EPI 0: BN+ReLU -> half2    EPI 1: BN+ReLU -> float2 addend
// EPI 2: tanh(acc + x) -> half2    EPI 3: tanh(acc + up) -> half2 + d_out fp32
template <int CIN, bool CIRC, int EPI>
__global__ void __launch_bounds__(512, 1)
convh_k(const unsigned* __restrict__ in, const unsigned* __restrict__ wp,
        const float* __restrict__ gm, const float* __restrict__ bt,
        const float* __restrict__ add, unsigned* __restrict__ outH,
        float* __restrict__ outF, float* __restrict__ out2, int tstep) {
    constexpr int KP = CIN / 2, KT = CIN / 16;
    extern __shared__ unsigned smu[];
    unsigned* As = smu;                  // [KP][872]
    unsigned* Ws = smu + KP * 872;       // [KT*9*8 rows][100]

    int img = blockIdx.y, ry0 = blockIdx.x * 8;
    int tid = threadIdx.x;
    int w = tid >> 5, qp = (tid >> 2) & 7, qt = tid & 3;
    int row = w >> 1, xhalf = w & 1;
    int vy = 0, vx = 0;
    if (CIRC) { int v = img % NV; vy = v / 3 - 1; vx = v % 3 - 1; }
    const unsigned* inI = in + (size_t)img * KP * PIX;
    uint32_t smA = (uint32_t)__cvta_generic_to_shared(As);
    uint32_t smW = (uint32_t)__cvta_generic_to_shared(Ws);

    // ---- stage A: rows ry0-2..ry0+9, cols -2..65 (wrap or zero) ----
    for (int i = tid; i < KP * 216; i += 512) {      // KP x 12 rows x 18 slots
        int k = i / 216, rem = i - k * 216, r = rem / 18, s = rem - r * 18;
        int gy = ry0 + r - 2;
        bool rowok = true;
        if (CIRC) gy &= 63; else rowok = (gy >= 0 && gy < 64);
        const unsigned* srow = inI + (size_t)k * PIX + gy * 64;
        uint32_t dst = smA + (uint32_t)(k * 872 + r * 72) * 4u;
        if (s < 16)       cp16(dst + (4 + s * 4) * 4, srow + s * 4, rowok ? 16 : 0);
        else if (s == 16) cp8(dst + 2 * 4, srow + 62, (CIRC && rowok) ? 8 : 0);
        else              cp8(dst + 68 * 4, srow,     (CIRC && rowok) ? 8 : 0);
    }
    // ---- stage all 9 tap weight images (linear copy) ----
    for (int i = tid; i < KT * 9 * 8 * 25; i += 512)
        cp16(smW + i * 16, wp + i * 4, 16);
    CP_COMMIT(); CP_WAIT0(); __syncthreads();

    float acc[2][8][4];
#pragma unroll
    for (int mt = 0; mt < 2; mt++)
#pragma unroll
        for (int g = 0; g < 8; g++)
#pragma unroll
            for (int j = 0; j < 4; j++) acc[mt][g][j] = 0.f;

    int mbase = (2 + row) * 72 + 4 + 32 * xhalf + qp;

#pragma unroll
    for (int tap = 0; tap < 9; tap++) {
        int dy = tap / 3, dx = tap - dy * 3;
        int apos = mbase + (dy - 1 + vy) * 72 + (dx - 1 + vx);
#pragma unroll
        for (int kt = 0; kt < KT; kt++) {
            int wr = ((tap * KT + kt) * 8 + qt) * 100 + qp * 12;
            uint4 L0 = *(const uint4*)(Ws + wr);
            uint4 L1 = *(const uint4*)(Ws + wr + 4);
            uint4 L2 = *(const uint4*)(Ws + wr + 4 * 100);
            uint4 L3 = *(const uint4*)(Ws + wr + 4 * 100 + 4);
            unsigned b0[8] = {L0.x, L0.y, L0.z, L0.w, L1.x, L1.y, L1.z, L1.w};
            unsigned b1[8] = {L2.x, L2.y, L2.z, L2.w, L3.x, L3.y, L3.z, L3.w};
            int ar0 = (kt * 8 + qt) * 872, ar2 = ar0 + 4 * 872;
#pragma unroll
            for (int mt = 0; mt < 2; mt++) {
                int base = apos + mt * 16;
                unsigned a0 = As[ar0 + base], a1 = As[ar0 + base + 8];
                unsigned a2 = As[ar2 + base], a3 = As[ar2 + base + 8];
#pragma unroll
                for (int g = 0; g < 8; g++)
                    mma16(acc[mt][g], a0, a1, a2, a3, b0[g], b1[g]);
            }
        }
    }

    // ---- epilogue ----
    int y = ry0 + row;
#pragma unroll
    for (int mt = 0; mt < 2; mt++) {
        int x0 = 32 * xhalf + qp + mt * 16;
        int pixA = y * 64 + x0, pixB = pixA + 8;
#pragma unroll
        for (int g = 0; g < 8; g++) {
            int kp = g * 4 + qt, c = kp * 2;
            float v0 = acc[mt][g][0], v1 = acc[mt][g][1];
            float v2 = acc[mt][g][2], v3 = acc[mt][g][3];
            if (EPI == 0 || EPI == 1) {
                float s0 = gm[c] * BNS_C, s1 = gm[c+1] * BNS_C;
                float o0 = bt[c], o1 = bt[c+1];
                v0 = fmaxf(v0 * s0 + o0, 0.f); v1 = fmaxf(v1 * s1 + o1, 0.f);
                v2 = fmaxf(v2 * s0 + o0, 0.f); v3 = fmaxf(v3 * s1 + o1, 0.f);
                if (EPI == 0) {
                    unsigned* o = outH + ((size_t)img * 32 + kp) * PIX;
                    o[pixA] = packh(v0, v1); o[pixB] = packh(v2, v3);
                } else {
                    float2* o = (float2*)outF + ((size_t)img * 32 + kp) * PIX;
                    o[pixA] = make_float2(v0, v1); o[pixB] = make_float2(v2, v3);
                }
            } else {
                const float2* a = (const float2*)add +
                    ((EPI == 2) ? ((size_t)(tstep * 4 + img / NV) * 32 + kp) * PIX
                                : ((size_t)img * 32 + kp) * PIX);
                float2 xa = a[pixA], xb = a[pixB];
                float t0 = tanhf(v0 + xa.x), t1 = tanhf(v1 + xa.y);
                float t2 = tanhf(v2 + xb.x), t3 = tanhf(v3 + xb.y);
                unsigned* o = outH + ((size_t)img * 32 + kp) * PIX;
                o[pixA] = packh(t0, t1); o[pixB] = packh(t2, t3);
                if (EPI == 3) {
                    int v9 = img % NV, bb = img / NV;
                    float* q = out2 + (((size_t)(v9 * 4 + bb) * 64 + c) * 8 + tstep) * PIX;
                    q[pixA] = t0; q[pixB] = t2;
                    q += 8 * PIX;
                    q[pixA] = t1; q[pixB] = t3;
                }
            }
        }
    }
}

// ---------------- host driver -------------------------------------------------
extern "C" void kernel_launch(void* const* d_in, const int* in_sizes, int n_in,
                              void* d_out, int out_size) {
    (void)in_sizes; (void)n_in; (void)out_size;
    const float* u   = (const float*)d_in[0];
    const float* w1  = (const float*)d_in[1];
    const float* g1  = (const float*)d_in[2];
    const float* b1  = (const float*)d_in[3];
    const float* w2  = (const float*)d_in[4];
    const float* g2  = (const float*)d_in[5];
    const float* b2  = (const float*)d_in[6];
    const float* w3  = (const float*)d_in[7];
    const float* g3  = (const float*)d_in[8];
    const float* b3  = (const float*)d_in[9];
    const float* wul = (const float*)d_in[10];
    const float* gul = (const float*)d_in[11];
    const float* bul = (const float*)d_in[12];
    const float* wh0 = (const float*)d_in[13];
    const float* wh1 = (const float*)d_in[14];
    float* out = (float*)d_out;

    const int SM64B = (32 * 872 + 288 * 100) * 4;   // 226816
    const int SM32B = (16 * 872 + 144 * 100) * 4;   // 113408

    static unsigned *pe1 = nullptr, *pe2, *ph0, *ph1,
                    *pw2, *pw3, *pwul, *pwh0, *pwh1;
    static float *px, *pup;
    if (!pe1) {   // pointer caching + attrs; runs on the pre-capture call
        cudaGetSymbolAddress((void**)&pe1,  g_e1);
        cudaGetSymbolAddress((void**)&pe2,  g_e2);
        cudaGetSymbolAddress((void**)&ph0,  g_h0);
        cudaGetSymbolAddress((void**)&ph1,  g_h1);
        cudaGetSymbolAddress((void**)&px,   g_x);
        cudaGetSymbolAddress((void**)&pup,  g_up);
        cudaGetSymbolAddress((void**)&pw2,  g_wp2);
        cudaGetSymbolAddress((void**)&pw3,  g_wp3);
        cudaGetSymbolAddress((void**)&pwul, g_wpul);
        cudaGetSymbolAddress((void**)&pwh0, g_wph0);
        cudaGetSymbolAddress((void**)&pwh1, g_wph1);
        cudaFuncSetAttribute(convh_k<32, false, 0>,
                             cudaFuncAttributeMaxDynamicSharedMemorySize, SM32B);
        cudaFuncSetAttribute(convh_k<64, false, 1>,
                             cudaFuncAttributeMaxDynamicSharedMemorySize, SM64B);
        cudaFuncSetAttribute(convh_k<64, true, 2>,
                             cudaFuncAttributeMaxDynamicSharedMemorySize, SM64B);
        cudaFuncSetAttribute(convh_k<64, true, 3>,
                             cudaFuncAttributeMaxDynamicSharedMemorySize, SM64B);
    }
    const size_t HSZ = 36ull * 32 * PIX;   // h buffer parity size (u32 units)

    // zero parity-0 h states (half2 zeros == bit-zero)
    zero4_k<<<1536, 256>>>((float4*)ph0, (long)HSZ / 4);
    zero4_k<<<1536, 256>>>((float4*)ph1, (long)HSZ / 4);
    prep_w_k<<<dim3(72, 5), 256>>>(w2, w3, wul, wh0, wh1);

    // encoder
    conv1_k<<<dim3(16, 32), 256>>>(u, w1, g1, b1, pe1);
    convh_k<32, false, 0><<<dim3(8, 32), 512, SM32B>>>(
        pe1, pw2, g2, b2, nullptr, pe2, nullptr, nullptr, 0);
    convh_k<64, false, 1><<<dim3(8, 32), 512, SM64B>>>(
        pe2, pw3, g3, b3, nullptr, nullptr, px, nullptr, 0);

    // recurrent steps
    for (int t = 0; t < 8; t++) {
        int rp = t & 1, wpp = 1 - rp;
        // h0 = tanh(x_t + circ-shift conv(h0_old, w_h0))
        convh_k<64, true, 2><<<dim3(8, 36), 512, SM64B>>>(
            ph0 + rp * HSZ, pwh0, nullptr, nullptr, px,
            ph0 + wpp * HSZ, nullptr, nullptr, t);
        // up = relu(bn(conv(h0_new, w_ul)))  (zero pad, float2 addend out)
        convh_k<64, false, 1><<<dim3(8, 36), 512, SM64B>>>(
            ph0 + wpp * HSZ, pwul, gul, bul, nullptr, nullptr, pup, nullptr, 0);
        // h1 = tanh(up + circ-shift conv(h1_old, w_h1)); fused d_out store
        convh_k<64, true, 3><<<dim3(8, 36), 512, SM64B>>>(
            ph1 + rp * HSZ, pwh1, nullptr, nullptr, pup,
            ph1 + wpp * HSZ, nullptr, out, t);
    }
}

// round 9
// speedup vs baseline: 3.8627x; 1.1089x over previous
#include <cuda_runtime.h>
#include <cuda_fp16.h>
#include <math.h>
#include <stdint.h>

#define PIX 4096
#define NV 9

// ---------------- scratch (device globals; half2 feature buffers) ------------
__device__ unsigned g_e1[32ull*16*PIX];     // encoder stage1, 32ch = 16 kpairs
__device__ unsigned g_e2[32ull*32*PIX];     // encoder stage2, 64ch = 32 kpairs
__device__ unsigned g_h0[2ull*36*32*PIX];   // ping-pong h0 (half2)
__device__ unsigned g_h1[2ull*36*32*PIX];   // ping-pong h1 (half2)
__device__ float    g_x [32ull*32*PIX*2];   // fp32 addend x, float2-interleaved
__device__ float    g_up[36ull*32*PIX*2];   // fp32 addend up
// pre-permuted half2 weights, kt-major conflict-free image (row stride 100 u32)
__device__ unsigned g_wp2 [144*100];
__device__ unsigned g_wp3 [288*100];
__device__ unsigned g_wpul[288*100];
__device__ unsigned g_wph0[288*100];
__device__ unsigned g_wph1[288*100];

// ---------------- helpers -----------------------------------------------------
__device__ __forceinline__ void cp16(uint32_t s, const void* g, int srcsz) {
    asm volatile("cp.async.ca.shared.global [%0], [%1], 16, %2;"
                 :: "r"(s), "l"(g), "r"(srcsz));
}
__device__ __forceinline__ void cp8(uint32_t s, const void* g, int srcsz) {
    asm volatile("cp.async.ca.shared.global [%0], [%1], 8, %2;"
                 :: "r"(s), "l"(g), "r"(srcsz));
}
#define CP_COMMIT() asm volatile("cp.async.commit_group;")
#define CP_WAIT1()  asm volatile("cp.async.wait_group 1;" ::: "memory")
#define CP_WAIT0()  asm volatile("cp.async.wait_group 0;" ::: "memory")

__device__ __forceinline__ void mma16(float* d, unsigned a0, unsigned a1,
                                      unsigned a2, unsigned a3,
                                      unsigned b0, unsigned b1) {
    asm("mma.sync.aligned.m16n8k16.row.col.f32.f16.f16.f32 "
        "{%0,%1,%2,%3},{%4,%5,%6,%7},{%8,%9},{%0,%1,%2,%3};"
        : "+f"(d[0]), "+f"(d[1]), "+f"(d[2]), "+f"(d[3])
        : "r"(a0), "r"(a1), "r"(a2), "r"(a3), "r"(b0), "r"(b1));
}
__device__ __forceinline__ unsigned packh(float a, float b) {
    __half2 h = __halves2half2(__float2half_rn(a), __float2half_rn(b));
    return *(unsigned*)&h;
}
__device__ __forceinline__ unsigned long long ffma2(unsigned long long a,
                                                    unsigned long long b,
                                                    unsigned long long c) {
    unsigned long long d;
    asm("fma.rn.f32x2 %0, %1, %2, %3;" : "=l"(d) : "l"(a), "l"(b), "l"(c));
    return d;
}
__device__ __forceinline__ unsigned long long pack_dup(float v) {
    unsigned long long d; unsigned r = __float_as_uint(v);
    asm("mov.b64 %0, {%1, %1};" : "=l"(d) : "r"(r));
    return d;
}
__device__ __forceinline__ void unpack2(unsigned long long v, float& lo, float& hi) {
    unsigned a, b;
    asm("mov.b64 {%0, %1}, %2;" : "=r"(a), "=r"(b) : "l"(v));
    lo = __uint_as_float(a); hi = __uint_as_float(b);
}
__constant__ float BNS_C = 0.9999950000374996f;   // 1/sqrt(1+1e-5)

// weights -> half2, kt-major: row = (kt*9+tap)*8+kp8 (stride 100), col gid*12+g
__global__ void prep_w_k(const float* __restrict__ w2, const float* __restrict__ w3,
                         const float* __restrict__ wul, const float* __restrict__ wh0,
                         const float* __restrict__ wh1) {
    int idx = blockIdx.x * 256 + threadIdx.x, conv = blockIdx.y;
    const float* src; unsigned* dst; int CIN;
    if      (conv == 0) { src = w2;  dst = g_wp2;  CIN = 32; }
    else if (conv == 1) { src = w3;  dst = g_wp3;  CIN = 64; }
    else if (conv == 2) { src = wul; dst = g_wpul; CIN = 64; }
    else if (conv == 3) { src = wh0; dst = g_wph0; CIN = 64; }
    else                { src = wh1; dst = g_wph1; CIN = 64; }
    int KP = CIN >> 1;
    if (idx >= 9 * KP * 64) return;
    int tap = idx / (KP * 64), rem = idx - tap * (KP * 64);
    int kp = rem >> 6, n = rem & 63;
    int kt = kp >> 3, kp8 = kp & 7, gid = n & 7, g = n >> 3;
    float lo = src[((size_t)n * CIN + 2 * kp) * 9 + tap];
    float hi = src[((size_t)n * CIN + 2 * kp + 1) * 9 + tap];
    dst[((kt * 9 + tap) * 8 + kp8) * 100 + gid * 12 + g] = packh(lo, hi);
}

// ---------------- encoder conv1: 3->32, 5x5, quad-tiled f32x2 ----------------
__global__ void __launch_bounds__(256, 1)
conv1q_k(const float* __restrict__ u, const float* __restrict__ wt,
         const float* __restrict__ gm, const float* __restrict__ bt,
         unsigned* __restrict__ out) {
    __shared__ float sIn[3][1296];    // 3 x 36x36 (halo 2)
    __shared__ float sW[2400];        // [cin][tap25][cout32]
    int tile = blockIdx.x, e = blockIdx.y;      // e = t*4+b
    int tstep = e >> 2, bb = e & 3;
    int ty0 = (tile >> 1) << 5, tx0 = (tile & 1) << 5;
    int tid = threadIdx.x, lx = tid & 15, ly = tid >> 4;
    int qy = ly << 1, qx = lx << 1;
    const float* inI = u + (size_t)(bb * 8 + tstep) * 3 * PIX;
    for (int i = tid; i < 2400; i += 256) {
        int k = i / 800, r = i - k * 800, t5 = r >> 5, c = r & 31;
        sW[i] = wt[(c * 3 + k) * 25 + t5];
    }
    for (int i = tid; i < 3 * 1296; i += 256) {
        int k = i / 1296, rem = i - k * 1296, ry = rem / 36, rx = rem - ry * 36;
        int gy = ty0 + ry - 2, gx = tx0 + rx - 2;
        sIn[k][rem] = (gy >= 0 && gy < 64 && gx >= 0 && gx < 64)
                      ? inI[(size_t)k * PIX + gy * 64 + gx] : 0.f;
    }
    __syncthreads();

    unsigned long long acc[16][4];
#pragma unroll
    for (int p = 0; p < 16; p++)
#pragma unroll
        for (int j = 0; j < 4; j++) acc[p][j] = 0ull;

    for (int k = 0; k < 3; k++) {
        unsigned long long n2[36];
#pragma unroll
        for (int dy = 0; dy < 6; dy++)
#pragma unroll
            for (int dx = 0; dx < 6; dx++)
                n2[dy * 6 + dx] = pack_dup(sIn[k][(qy + dy) * 36 + qx + dx]);
#pragma unroll
        for (int t5 = 0; t5 < 25; t5++) {
            int dy = t5 / 5, dx = t5 - dy * 5;
            const unsigned long long* w2p =
                (const unsigned long long*)(sW + k * 800 + t5 * 32);
#pragma unroll
            for (int p = 0; p < 16; p++) {
                unsigned long long w = w2p[p];
#pragma unroll
                for (int py = 0; py < 2; py++)
#pragma unroll
                    for (int pxx = 0; pxx < 2; pxx++)
                        acc[p][py * 2 + pxx] =
                            ffma2(w, n2[(py + dy) * 6 + (pxx + dx)], acc[p][py * 2 + pxx]);
            }
        }
    }
    unsigned* o = out + (size_t)e * 16 * PIX;
#pragma unroll
    for (int p = 0; p < 16; p++) {
        int c = 2 * p;
        float s0 = gm[c] * BNS_C, o0 = bt[c];
        float s1 = gm[c + 1] * BNS_C, o1 = bt[c + 1];
#pragma unroll
        for (int py = 0; py < 2; py++)
#pragma unroll
            for (int pxx = 0; pxx < 2; pxx++) {
                float lo, hi;
                unpack2(acc[p][py * 2 + pxx], lo, hi);
                float r0 = fmaxf(lo * s0 + o0, 0.f), r1 = fmaxf(hi * s1 + o1, 0.f);
                o[(size_t)p * PIX + (ty0 + qy + py) * 64 + tx0 + qx + pxx] = packh(r0, r1);
            }
    }
}

// ---------------- t=0 shortcuts ----------------------------------------------
// h0(t=0) = tanh(x_0[b]) -- identical across all 9 velocities
__global__ void h0t0_k(const float* __restrict__ x, unsigned* __restrict__ h0) {
    int b = blockIdx.y;
    int i = blockIdx.x * 256 + threadIdx.x;          // < 32*PIX
    float2 xv = ((const float2*)x)[(size_t)b * 32 * PIX + i];
    unsigned hv = packh(tanhf(xv.x), tanhf(xv.y));
#pragma unroll
    for (int v = 0; v < 9; v++)
        h0[((size_t)(b * 9 + v) * 32) * PIX + i] = hv;
}
// h1(t=0) = tanh(up_0[b]) broadcast over v; also d_out at t=0
__global__ void h1t0_k(const float* __restrict__ up, unsigned* __restrict__ h1,
                       float* __restrict__ dout) {
    int b = blockIdx.y;
    int i = blockIdx.x * 256 + threadIdx.x;          // kp*PIX + pix
    int kp = i >> 12, pix = i & 4095, c = kp * 2;
    float2 uv = ((const float2*)up)[((size_t)(b * 9) * 32 + kp) * PIX + pix];
    float t0 = tanhf(uv.x), t1 = tanhf(uv.y);
    unsigned hv = packh(t0, t1);
#pragma unroll
    for (int v = 0; v < 9; v++) {
        h1[((size_t)(b * 9 + v) * 32 + kp) * PIX + pix] = hv;
        float* q = dout + (((size_t)(v * 4 + b) * 64 + c) * 8) * PIX;
        q[pix] = t0; q[8 * PIX + pix] = t1;
    }
}

// ---------------- fp16 tensor-core 3x3 conv, CIN->64 -------------------------
// Block 512 thr = 16 warps; 8 output rows x 64 px; warp = (row 0..7, xhalf).
// Split-stage: A/W in two commit groups (K-halves); kt-major mainloop starts
// on half 0 while half 1 is in flight. No other mainloop barriers.
template <int CIN, bool CIRC, int EPI>
__global__ void __launch_bounds__(512, 1)
convh_k(const unsigned* __restrict__ in, const unsigned* __restrict__ wp,
        const float* __restrict__ gm, const float* __restrict__ bt,
        const float* __restrict__ add, unsigned* __restrict__ outH,
        float* __restrict__ outF, float* __restrict__ out2, int tstep,
        int imgstep) {
    constexpr int KP = CIN / 2, KT = CIN / 16, KPH = KP / 2;
    constexpr int WHALF = (KT / 2) * 9 * 8 * 25;     // uint4 per W half
    extern __shared__ unsigned smu[];
    unsigned* As = smu;                  // [KP][872]
    unsigned* Ws = smu + KP * 872;       // [KT*9*8 rows][100]

    int img = blockIdx.y * imgstep, ry0 = blockIdx.x * 8;
    int tid = threadIdx.x;
    int w = tid >> 5, qp = (tid >> 2) & 7, qt = tid & 3;
    int row = w >> 1, xhalf = w & 1;
    int vy = 0, vx = 0;
    if (CIRC) { int v = img % NV; vy = v / 3 - 1; vx = v % 3 - 1; }
    const unsigned* inI = in + (size_t)img * KP * PIX;
    uint32_t smA = (uint32_t)__cvta_generic_to_shared(As);
    uint32_t smW = (uint32_t)__cvta_generic_to_shared(Ws);

    auto stageA = [&](int k0, int k1) {
        for (int i = k0 * 216 + tid; i < k1 * 216; i += 512) {
            int k = i / 216, rem = i - k * 216, r = rem / 18, s = rem - r * 18;
            int gy = ry0 + r - 2;
            bool rowok = true;
            if (CIRC) gy &= 63; else rowok = (gy >= 0 && gy < 64);
            const unsigned* srow = inI + (size_t)k * PIX + gy * 64;
            uint32_t dst = smA + (uint32_t)(k * 872 + r * 72) * 4u;
            if (s < 16)       cp16(dst + (4 + s * 4) * 4, srow + s * 4, rowok ? 16 : 0);
            else if (s == 16) cp8(dst + 2 * 4, srow + 62, (CIRC && rowok) ? 8 : 0);
            else              cp8(dst + 68 * 4, srow,     (CIRC && rowok) ? 8 : 0);
        }
    };
    stageA(0, KPH);
    for (int i = tid; i < WHALF; i += 512)
        cp16(smW + i * 16, wp + i * 4, 16);
    CP_COMMIT();
    stageA(KPH, KP);
    for (int i = tid; i < WHALF; i += 512)
        cp16(smW + (WHALF + i) * 16, wp + (WHALF + i) * 4, 16);
    CP_COMMIT();

    float acc[2][8][4];
#pragma unroll
    for (int mt = 0; mt < 2; mt++)
#pragma unroll
        for (int g = 0; g < 8; g++)
#pragma unroll
            for (int j = 0; j < 4; j++) acc[mt][g][j] = 0.f;

    int mbase = (2 + row) * 72 + 4 + 32 * xhalf + qp;

    CP_WAIT1(); __syncthreads();
#pragma unroll
    for (int kh = 0; kh < 2; kh++) {
        if (kh) { CP_WAIT0(); __syncthreads(); }
#pragma unroll
        for (int kt = kh * (KT / 2); kt < (kh + 1) * (KT / 2); kt++) {
#pragma unroll
            for (int tap = 0; tap < 9; tap++) {
                int dy = tap / 3, dx = tap - dy * 3;
                int apos = mbase + (dy - 1 + vy) * 72 + (dx - 1 + vx);
                int wr = ((kt * 9 + tap) * 8 + qt) * 100 + qp * 12;
                uint4 L0 = *(const uint4*)(Ws + wr);
                uint4 L1 = *(const uint4*)(Ws + wr + 4);
                uint4 L2 = *(const uint4*)(Ws + wr + 4 * 100);
                uint4 L3 = *(const uint4*)(Ws + wr + 4 * 100 + 4);
                unsigned b0[8] = {L0.x, L0.y, L0.z, L0.w, L1.x, L1.y, L1.z, L1.w};
                unsigned b1[8] = {L2.x, L2.y, L2.z, L2.w, L3.x, L3.y, L3.z, L3.w};
                int ar0 = (kt * 8 + qt) * 872, ar2 = ar0 + 4 * 872;
#pragma unroll
                for (int mt = 0; mt < 2; mt++) {
                    int base = apos + mt * 16;
                    unsigned a0 = As[ar0 + base], a1 = As[ar0 + base + 8];
                    unsigned a2 = As[ar2 + base], a3 = As[ar2 + base + 8];
#pragma unroll
                    for (int g = 0; g < 8; g++)
                        mma16(acc[mt][g], a0, a1, a2, a3, b0[g], b1[g]);
                }
            }
        }
    }

    // ---- epilogue ----
    int y = ry0 + row;
#pragma unroll
    for (int mt = 0; mt < 2; mt++) {
        int x0 = 32 * xhalf + qp + mt * 16;
        int pixA = y * 64 + x0, pixB = pixA + 8;
#pragma unroll
        for (int g = 0; g < 8; g++) {
            int kp = g * 4 + qt, c = kp * 2;
            float v0 = acc[mt][g][0], v1 = acc[mt][g][1];
            float v2 = acc[mt][g][2], v3 = acc[mt][g][3];
            if (EPI == 0 || EPI == 1) {
                float s0 = gm[c] * BNS_C, s1 = gm[c+1] * BNS_C;
                float o0 = bt[c], o1 = bt[c+1];
                v0 = fmaxf(v0 * s0 + o0, 0.f); v1 = fmaxf(v1 * s1 + o1, 0.f);
                v2 = fmaxf(v2 * s0 + o0, 0.f); v3 = fmaxf(v3 * s1 + o1, 0.f);
                if (EPI == 0) {
                    unsigned* o = outH + ((size_t)img * 32 + kp) * PIX;
                    o[pixA] = packh(v0, v1); o[pixB] = packh(v2, v3);
                } else {
                    float2* o = (float2*)outF + ((size_t)img * 32 + kp) * PIX;
                    o[pixA] = make_float2(v0, v1); o[pixB] = make_float2(v2, v3);
                }
            } else {
                const float2* a = (const float2*)add +
                    ((EPI == 2) ? ((size_t)(tstep * 4 + img / NV) * 32 + kp) * PIX
                                : ((size_t)img * 32 + kp) * PIX);
                float2 xa = a[pixA], xb = a[pixB];
                float t0 = tanhf(v0 + xa.x), t1 = tanhf(v1 + xa.y);
                float t2 = tanhf(v2 + xb.x), t3 = tanhf(v3 + xb.y);
                unsigned* o = outH + ((size_t)img * 32 + kp) * PIX;
                o[pixA] = packh(t0, t1); o[pixB] = packh(t2, t3);
                if (EPI == 3) {
                    int v9 = img % NV, bb = img / NV;
                    float* q = out2 + (((size_t)(v9 * 4 + bb) * 64 + c) * 8 + tstep) * PIX;
                    q[pixA] = t0; q[pixB] = t2;
                    q += 8 * PIX;
                    q[pixA] = t1; q[pixB] = t3;
                }
            }
        }
    }
}

// ---------------- host driver -------------------------------------------------
extern "C" void kernel_launch(void* const* d_in, const int* in_sizes, int n_in,
                              void* d_out, int out_size) {
    (void)in_sizes; (void)n_in; (void)out_size;
    const float* u   = (const float*)d_in[0];
    const float* w1  = (const float*)d_in[1];
    const float* g1  = (const float*)d_in[2];
    const float* b1  = (const float*)d_in[3];
    const float* w2  = (const float*)d_in[4];
    const float* g2  = (const float*)d_in[5];
    const float* b2  = (const float*)d_in[6];
    const float* w3  = (const float*)d_in[7];
    const float* g3  = (const float*)d_in[8];
    const float* b3  = (const float*)d_in[9];
    const float* wul = (const float*)d_in[10];
    const float* gul = (const float*)d_in[11];
    const float* bul = (const float*)d_in[12];
    const float* wh0 = (const float*)d_in[13];
    const float* wh1 = (const float*)d_in[14];
    float* out = (float*)d_out;

    const int SM64B = (32 * 872 + 288 * 100) * 4;   // 226816
    const int SM32B = (16 * 872 + 144 * 100) * 4;   // 113408

    static unsigned *pe1 = nullptr, *pe2, *ph0, *ph1,
                    *pw2, *pw3, *pwul, *pwh0, *pwh1;
    static float *px, *pup;
    if (!pe1) {   // pointer caching + attrs; runs on the pre-capture call
        cudaGetSymbolAddress((void**)&pe1,  g_e1);
        cudaGetSymbolAddress((void**)&pe2,  g_e2);
        cudaGetSymbolAddress((void**)&ph0,  g_h0);
        cudaGetSymbolAddress((void**)&ph1,  g_h1);
        cudaGetSymbolAddress((void**)&px,   g_x);
        cudaGetSymbolAddress((void**)&pup,  g_up);
        cudaGetSymbolAddress((void**)&pw2,  g_wp2);
        cudaGetSymbolAddress((void**)&pw3,  g_wp3);
        cudaGetSymbolAddress((void**)&pwul, g_wpul);
        cudaGetSymbolAddress((void**)&pwh0, g_wph0);
        cudaGetSymbolAddress((void**)&pwh1, g_wph1);
        cudaFuncSetAttribute(convh_k<32, false, 0>,
                             cudaFuncAttributeMaxDynamicSharedMemorySize, SM32B);
        cudaFuncSetAttribute(convh_k<64, false, 1>,
                             cudaFuncAttributeMaxDynamicSharedMemorySize, SM64B);
        cudaFuncSetAttribute(convh_k<64, true, 2>,
                             cudaFuncAttributeMaxDynamicSharedMemorySize, SM64B);
        cudaFuncSetAttribute(convh_k<64, true, 3>,
                             cudaFuncAttributeMaxDynamicSharedMemorySize, SM64B);
    }
    const size_t HSZ = 36ull * 32 * PIX;   // h buffer parity size (u32 units)

    prep_w_k<<<dim3(72, 5), 256>>>(w2, w3, wul, wh0, wh1);

    // encoder
    conv1q_k<<<dim3(4, 32), 256>>>(u, w1, g1, b1, pe1);
    convh_k<32, false, 0><<<dim3(8, 32), 512, SM32B>>>(
        pe1, pw2, g2, b2, nullptr, pe2, nullptr, nullptr, 0, 1);
    convh_k<64, false, 1><<<dim3(8, 32), 512, SM64B>>>(
        pe2, pw3, g3, b3, nullptr, nullptr, px, nullptr, 0, 1);

    // ---- t = 0 (hidden states zero): algebraic shortcut ----
    h0t0_k<<<dim3(512, 4), 256>>>(px, ph0 + HSZ);                 // parity 1
    convh_k<64, false, 1><<<dim3(8, 4), 512, SM64B>>>(            // up_0, 4 imgs
        ph0 + HSZ, pwul, gul, bul, nullptr, nullptr, pup, nullptr, 0, 9);
    h1t0_k<<<dim3(512, 4), 256>>>(pup, ph1 + HSZ, out);           // parity 1

    // ---- recurrent steps t = 1..7 ----
    for (int t = 1; t < 8; t++) {
        int rp = t & 1, wpp = 1 - rp;
        // h0 = tanh(x_t + circ-shift conv(h0_old, w_h0))
        convh_k<64, true, 2><<<dim3(8, 36), 512, SM64B>>>(
            ph0 + rp * HSZ, pwh0, nullptr, nullptr, px,
            ph0 + wpp * HSZ, nullptr, nullptr, t, 1);
        // up = relu(bn(conv(h0_new, w_ul)))  (zero pad, float2 addend out)
        convh_k<64, false, 1><<<dim3(8, 36), 512, SM64B>>>(
            ph0 + wpp * HSZ, pwul, gul, bul, nullptr, nullptr, pup, nullptr, 0, 1);
        // h1 = tanh(up + circ-shift conv(h1_old, w_h1)); fused d_out store
        convh_k<64, true, 3><<<dim3(8, 36), 512, SM64B>>>(
            ph1 + rp * HSZ, pwh1, nullptr, nullptr, pup,
            ph1 + wpp * HSZ, nullptr, out, t, 1);
    }
}